// round 2
// baseline (speedup 1.0000x reference)
#include <cuda_runtime.h>

// Problem constants
constexpr int Bb = 2, Sq = 2048, Dm = 1024, Hh = 16, Dh = 64;
constexpr int Mrows = Bb * Sq; // 4096

// Scratch (no cudaMalloc allowed) — __device__ globals
__device__ float g_q[Bb * Hh * Sq * Dh];     // [B,H,S,DH], pre-scaled by 1/sqrt(DH)
__device__ float g_k[Bb * Hh * Sq * Dh];
__device__ float g_v[Bb * Hh * Sq * Dh];
__device__ float g_attn[Bb * Sq * Dm];       // attention output, [B,S,D]
__device__ float g_Weff[Dm * Dm];
__device__ float g_beff[Dm];

// ---------------------------------------------------------------------------
// Collapse the NF=4 output projections into one: Weff = sum_f w[f] * Wout[f]
// ---------------------------------------------------------------------------
__global__ void combine_kernel(const float* __restrict__ w,
                               const float* __restrict__ Wout,
                               const float* __restrict__ bout) {
    int i = blockIdx.x * blockDim.x + threadIdx.x;
    float w0 = w[0], w1 = w[1], w2 = w[2], w3 = w[3];
    if (i < Dm * Dm) {
        g_Weff[i] = w0 * Wout[i] + w1 * Wout[i + Dm * Dm]
                  + w2 * Wout[i + 2 * Dm * Dm] + w3 * Wout[i + 3 * Dm * Dm];
    }
    if (i < Dm) {
        g_beff[i] = w0 * bout[i] + w1 * bout[i + Dm]
                  + w2 * bout[i + 2 * Dm] + w3 * bout[i + 3 * Dm];
    }
}

// ---------------------------------------------------------------------------
// NT GEMM: C[m,n] = sum_k A[m,k] * W[n,k]  (both K-contiguous)
// 64x64 tile, BK=16, 256 threads, 4x4 microtile.
// z selects Q/K/V; epilogue writes head-split [B,H,S,DH] layout,
// Q pre-scaled by 1/sqrt(DH)=0.125 (folds the softmax scale).
// ---------------------------------------------------------------------------
__global__ __launch_bounds__(256) void proj_kernel(
    const float* __restrict__ X,
    const float* __restrict__ Wq, const float* __restrict__ bq,
    const float* __restrict__ Wk, const float* __restrict__ bk,
    const float* __restrict__ Wv, const float* __restrict__ bv)
{
    const int z = blockIdx.z;
    const float* W    = (z == 0) ? Wq : (z == 1) ? Wk : Wv;
    const float* bias = (z == 0) ? bq : (z == 1) ? bk : bv;
    float* out        = (z == 0) ? g_q : (z == 1) ? g_k : g_v;
    const float scale = (z == 0) ? 0.125f : 1.0f;

    __shared__ float As[16][68];
    __shared__ float Bs[16][68];

    const int tid = threadIdx.x;
    const int ty = tid >> 4, tx = tid & 15;
    const int rowBase = blockIdx.y * 64;
    const int colBase = blockIdx.x * 64;
    const int lr = tid >> 2;          // 0..63 tile row to load
    const int lc = (tid & 3) << 2;    // 0,4,8,12 k offset

    float acc[4][4] = {};

    const float* Ap = X + (rowBase + lr) * Dm + lc;
    const float* Bp = W + (colBase + lr) * Dm + lc;

    for (int k0 = 0; k0 < Dm; k0 += 16) {
        float4 av  = *(const float4*)(Ap + k0);
        float4 bv4 = *(const float4*)(Bp + k0);
        __syncthreads();
        As[lc + 0][lr] = av.x;  As[lc + 1][lr] = av.y;
        As[lc + 2][lr] = av.z;  As[lc + 3][lr] = av.w;
        Bs[lc + 0][lr] = bv4.x; Bs[lc + 1][lr] = bv4.y;
        Bs[lc + 2][lr] = bv4.z; Bs[lc + 3][lr] = bv4.w;
        __syncthreads();
#pragma unroll
        for (int kk = 0; kk < 16; kk++) {
            float4 a4 = *(const float4*)&As[kk][ty << 2];
            float4 b4 = *(const float4*)&Bs[kk][tx << 2];
            float a[4] = {a4.x, a4.y, a4.z, a4.w};
            float b[4] = {b4.x, b4.y, b4.z, b4.w};
#pragma unroll
            for (int i = 0; i < 4; i++)
#pragma unroll
                for (int j = 0; j < 4; j++)
                    acc[i][j] += a[i] * b[j];
        }
    }

    const int n0 = colBase + (tx << 2);
    const int h_ = n0 >> 6;           // head (tx*4..+3 stay within one head)
    float4 bsv = *(const float4*)(bias + n0);
    float bvv[4] = {bsv.x, bsv.y, bsv.z, bsv.w};
#pragma unroll
    for (int i = 0; i < 4; i++) {
        int m  = rowBase + (ty << 2) + i;
        int b_ = m >> 11;             // / 2048
        int s_ = m & 2047;
        float4 r;
        r.x = (acc[i][0] + bvv[0]) * scale;
        r.y = (acc[i][1] + bvv[1]) * scale;
        r.z = (acc[i][2] + bvv[2]) * scale;
        r.w = (acc[i][3] + bvv[3]) * scale;
        *(float4*)(out + ((b_ * Hh + h_) * Sq + s_) * Dh + (n0 & 63)) = r;
    }
}

// ---------------------------------------------------------------------------
// Flash attention, fp32, causal. BQ=BKV=64, DH=64, 256 threads.
// Thread (ty,tx): owns q rows ty*4..+3; tx indexes kv cols (QK phase)
// and dh cols (PV phase). P goes through smem (aliases K tile).
// ---------------------------------------------------------------------------
constexpr int ATS = 68;                         // padded row stride (floats)
constexpr int AT_SMEM_FLOATS = 3 * 64 * ATS;    // Q, K(=P), V tiles

__global__ __launch_bounds__(256) void attn_kernel()
{
    extern __shared__ float sm[];
    float (*Qs)[ATS] = (float(*)[ATS])sm;
    float (*Ks)[ATS] = (float(*)[ATS])(sm + 64 * ATS);
    float (*Vs)[ATS] = (float(*)[ATS])(sm + 2 * 64 * ATS);
    float (*Ps)[ATS] = Ks;                      // alias: P overwrites K tile

    const int tid = threadIdx.x;
    const int ty = tid >> 4, tx = tid & 15;
    const int qt = blockIdx.x;
    const int bh = blockIdx.y;
    const int qbase = qt * 64;

    const float* Qg = g_q + (bh * Sq + qbase) * Dh;
    for (int t = tid; t < 64 * 16; t += 256) {
        int r = t >> 4, c = (t & 15) << 2;
        *(float4*)&Qs[r][c] = *(const float4*)(Qg + r * Dh + c);
    }

    float m_i[4], l_i[4], o[4][4];
#pragma unroll
    for (int i = 0; i < 4; i++) {
        m_i[i] = -1e30f; l_i[i] = 0.f;
#pragma unroll
        for (int j = 0; j < 4; j++) o[i][j] = 0.f;
    }

    for (int kt = 0; kt <= qt; kt++) {
        const float* Kg = g_k + (bh * Sq + kt * 64) * Dh;
        const float* Vg = g_v + (bh * Sq + kt * 64) * Dh;
        __syncthreads();                        // prev tile fully consumed (also orders Q tile on iter 0)
        for (int t = tid; t < 64 * 16; t += 256) {
            int r = t >> 4, c = (t & 15) << 2;
            *(float4*)&Ks[r][c] = *(const float4*)(Kg + r * Dh + c);
            *(float4*)&Vs[r][c] = *(const float4*)(Vg + r * Dh + c);
        }
        __syncthreads();

        // S = Q @ K^T (Q pre-scaled)
        float s[4][4] = {};
#pragma unroll
        for (int d4 = 0; d4 < 16; d4++) {
            float4 q4[4], k4[4];
#pragma unroll
            for (int i = 0; i < 4; i++) q4[i] = *(const float4*)&Qs[(ty << 2) + i][d4 << 2];
#pragma unroll
            for (int j = 0; j < 4; j++) k4[j] = *(const float4*)&Ks[(tx << 2) + j][d4 << 2];
#pragma unroll
            for (int i = 0; i < 4; i++)
#pragma unroll
                for (int j = 0; j < 4; j++)
                    s[i][j] += q4[i].x * k4[j].x + q4[i].y * k4[j].y
                             + q4[i].z * k4[j].z + q4[i].w * k4[j].w;
        }

        if (kt == qt) {                         // diagonal tile: causal mask
#pragma unroll
            for (int i = 0; i < 4; i++)
#pragma unroll
                for (int j = 0; j < 4; j++)
                    if ((tx << 2) + j > (ty << 2) + i) s[i][j] = -1e30f;
        }

        // Online softmax: row stats reduced across the 16 lanes of each row group
#pragma unroll
        for (int i = 0; i < 4; i++) {
            float mloc = fmaxf(fmaxf(s[i][0], s[i][1]), fmaxf(s[i][2], s[i][3]));
#pragma unroll
            for (int off = 8; off > 0; off >>= 1)
                mloc = fmaxf(mloc, __shfl_xor_sync(0xffffffffu, mloc, off));
            float mnew = fmaxf(m_i[i], mloc);
            float corr = __expf(m_i[i] - mnew);
            float rsum = 0.f;
#pragma unroll
            for (int j = 0; j < 4; j++) {
                s[i][j] = __expf(s[i][j] - mnew);
                rsum += s[i][j];
            }
#pragma unroll
            for (int off = 8; off > 0; off >>= 1)
                rsum += __shfl_xor_sync(0xffffffffu, rsum, off);
            l_i[i] = l_i[i] * corr + rsum;
            m_i[i] = mnew;
#pragma unroll
            for (int j = 0; j < 4; j++) o[i][j] *= corr;
        }

        __syncthreads();                        // everyone done reading Ks before Ps overwrite
#pragma unroll
        for (int i = 0; i < 4; i++)
#pragma unroll
            for (int j = 0; j < 4; j++)
                Ps[(ty << 2) + i][(tx << 2) + j] = s[i][j];
        __syncthreads();

        // O += P @ V
#pragma unroll
        for (int k4 = 0; k4 < 16; k4++) {
            float4 p4[4], v4[4];
#pragma unroll
            for (int i = 0; i < 4; i++)  p4[i] = *(const float4*)&Ps[(ty << 2) + i][k4 << 2];
#pragma unroll
            for (int t2 = 0; t2 < 4; t2++) v4[t2] = *(const float4*)&Vs[(k4 << 2) + t2][tx << 2];
#pragma unroll
            for (int i = 0; i < 4; i++) {
                float p[4] = {p4[i].x, p4[i].y, p4[i].z, p4[i].w};
#pragma unroll
                for (int t2 = 0; t2 < 4; t2++) {
                    o[i][0] += p[t2] * v4[t2].x;
                    o[i][1] += p[t2] * v4[t2].y;
                    o[i][2] += p[t2] * v4[t2].z;
                    o[i][3] += p[t2] * v4[t2].w;
                }
            }
        }
    }

    const int b_ = bh >> 4, h_ = bh & 15;
#pragma unroll
    for (int i = 0; i < 4; i++) {
        int srow = qbase + (ty << 2) + i;
        float inv = 1.0f / l_i[i];
        float4 r;
        r.x = o[i][0] * inv; r.y = o[i][1] * inv;
        r.z = o[i][2] * inv; r.w = o[i][3] * inv;
        *(float4*)(g_attn + (b_ * Sq + srow) * Dm + h_ * Dh + (tx << 2)) = r;
    }
}

// ---------------------------------------------------------------------------
// Output projection: out = g_attn @ Weff^T + beff  (same NT GEMM, plain epilogue)
// ---------------------------------------------------------------------------
__global__ __launch_bounds__(256) void outproj_kernel(float* __restrict__ Out)
{
    __shared__ float As[16][68];
    __shared__ float Bs[16][68];

    const int tid = threadIdx.x;
    const int ty = tid >> 4, tx = tid & 15;
    const int rowBase = blockIdx.y * 64;
    const int colBase = blockIdx.x * 64;
    const int lr = tid >> 2;
    const int lc = (tid & 3) << 2;

    float acc[4][4] = {};

    const float* Ap = g_attn + (rowBase + lr) * Dm + lc;
    const float* Bp = g_Weff + (colBase + lr) * Dm + lc;

    for (int k0 = 0; k0 < Dm; k0 += 16) {
        float4 av  = *(const float4*)(Ap + k0);
        float4 bv4 = *(const float4*)(Bp + k0);
        __syncthreads();
        As[lc + 0][lr] = av.x;  As[lc + 1][lr] = av.y;
        As[lc + 2][lr] = av.z;  As[lc + 3][lr] = av.w;
        Bs[lc + 0][lr] = bv4.x; Bs[lc + 1][lr] = bv4.y;
        Bs[lc + 2][lr] = bv4.z; Bs[lc + 3][lr] = bv4.w;
        __syncthreads();
#pragma unroll
        for (int kk = 0; kk < 16; kk++) {
            float4 a4 = *(const float4*)&As[kk][ty << 2];
            float4 b4 = *(const float4*)&Bs[kk][tx << 2];
            float a[4] = {a4.x, a4.y, a4.z, a4.w};
            float b[4] = {b4.x, b4.y, b4.z, b4.w};
#pragma unroll
            for (int i = 0; i < 4; i++)
#pragma unroll
                for (int j = 0; j < 4; j++)
                    acc[i][j] += a[i] * b[j];
        }
    }

    const int n0 = colBase + (tx << 2);
    float4 bsv = *(const float4*)(g_beff + n0);
    float bvv[4] = {bsv.x, bsv.y, bsv.z, bsv.w};
#pragma unroll
    for (int i = 0; i < 4; i++) {
        int m = rowBase + (ty << 2) + i;
        float4 r;
        r.x = acc[i][0] + bvv[0];
        r.y = acc[i][1] + bvv[1];
        r.z = acc[i][2] + bvv[2];
        r.w = acc[i][3] + bvv[3];
        *(float4*)(Out + m * Dm + n0) = r;
    }
}

// ---------------------------------------------------------------------------
extern "C" void kernel_launch(void* const* d_in, const int* in_sizes, int n_in,
                              void* d_out, int out_size) {
    const float* x    = (const float*)d_in[0];
    const float* w    = (const float*)d_in[1];
    const float* Wq   = (const float*)d_in[2];
    const float* bq   = (const float*)d_in[3];
    const float* Wk   = (const float*)d_in[4];
    const float* bk   = (const float*)d_in[5];
    const float* Wv   = (const float*)d_in[6];
    const float* bv   = (const float*)d_in[7];
    const float* Wout = (const float*)d_in[8];
    const float* bout = (const float*)d_in[9];
    float* out = (float*)d_out;

    combine_kernel<<<(Dm * Dm + 255) / 256, 256>>>(w, Wout, bout);
    proj_kernel<<<dim3(Dm / 64, Mrows / 64, 3), 256>>>(x, Wq, bq, Wk, bk, Wv, bv);
    cudaFuncSetAttribute(attn_kernel, cudaFuncAttributeMaxDynamicSharedMemorySize,
                         AT_SMEM_FLOATS * sizeof(float));
    attn_kernel<<<dim3(Sq / 64, Bb * Hh), 256, AT_SMEM_FLOATS * sizeof(float)>>>();
    outproj_kernel<<<dim3(Dm / 64, Mrows / 64), 256>>>(out);
}

// round 4
// speedup vs baseline: 2.7335x; 2.7335x over previous
#include <cuda_runtime.h>
#include <cstdint>

// Problem constants
constexpr int Bb = 2, Sq = 2048, Dm = 1024, Hh = 16, Dh = 64;
constexpr int Mrows = Bb * Sq; // 4096

// Scratch (no cudaMalloc allowed)
__device__ float g_q[Bb * Hh * Sq * Dh];     // [B,H,S,DH], Q pre-scaled by 1/8
__device__ float g_k[Bb * Hh * Sq * Dh];
__device__ float g_v[Bb * Hh * Sq * Dh];
__device__ float g_attn[Bb * Sq * Dm];
__device__ float g_Weff[Dm * Dm];
__device__ float g_beff[Dm];

// ===================== mma.sync tf32 helpers (sm_80+ path) =====================
__device__ __forceinline__ uint32_t f2tf32(float f) {
    uint32_t r;
    asm("cvt.rna.tf32.f32 %0, %1;" : "=r"(r) : "f"(f));
    return r;
}
// D = A(16x8, tf32) * B(8x8, tf32) + D, fp32 accum
__device__ __forceinline__ void mma8(float* c, const uint32_t* a, const uint32_t* b) {
    asm volatile(
        "mma.sync.aligned.m16n8k8.row.col.f32.tf32.tf32.f32 "
        "{%0,%1,%2,%3}, {%4,%5,%6,%7}, {%8,%9}, {%0,%1,%2,%3};"
        : "+f"(c[0]), "+f"(c[1]), "+f"(c[2]), "+f"(c[3])
        : "r"(a[0]), "r"(a[1]), "r"(a[2]), "r"(a[3]), "r"(b[0]), "r"(b[1]));
}

// ===================== combine: Weff = sum_f w[f]*Wout[f] =====================
__global__ void combine_kernel(const float* __restrict__ w,
                               const float* __restrict__ Wout,
                               const float* __restrict__ bout) {
    int i = blockIdx.x * blockDim.x + threadIdx.x;
    float w0 = w[0], w1 = w[1], w2 = w[2], w3 = w[3];
    if (i < Dm * Dm) {
        g_Weff[i] = w0 * Wout[i] + w1 * Wout[i + Dm * Dm]
                  + w2 * Wout[i + 2 * Dm * Dm] + w3 * Wout[i + 3 * Dm * Dm];
    }
    if (i < Dm) {
        g_beff[i] = w0 * bout[i] + w1 * bout[i + Dm]
                  + w2 * bout[i + 2 * Dm] + w3 * bout[i + 3 * Dm];
    }
}

// ===================== tf32 NT GEMM: C[m,n] = A[m,:]·W[n,:] =====================
// 128x128 CTA tile, 8 warps (warp tile 64x32), BK=32, double-buffered tf32 smem.
constexpr int BM = 128, BN = 128, BK = 32;
constexpr int SKS = BK + 4;                     // padded stride (uints)
constexpr int HALF = BM * SKS;                  // one matrix per stage (uints)
constexpr int STAGE = 2 * HALF;                 // A+B per stage
constexpr int GEMM_DYN = 2 * STAGE * 4;         // bytes (73728)
constexpr int NSTAGE = Dm / BK;                 // 32

struct EpiNone {};

template <int MODE>  // 0 = head-split QKV epilogue, 1 = plain
__device__ __forceinline__ void gemm_core(
    const float* __restrict__ A, const float* __restrict__ W,
    const float* __restrict__ bias, float scale, float* __restrict__ out,
    int rowBase, int colBase)
{
    extern __shared__ uint32_t smg[];
    const int tid = threadIdx.x, wid = tid >> 5, lane = tid & 31;
    const int lq = lane >> 2, lr = lane & 3;
    const int warpM = wid & 1, warpN = wid >> 1;       // 2 x 4 warps

    // load mapping: 2 threads per row, 16 floats each
    const int row = tid >> 1;
    const int kh = (tid & 1) << 4;
    const float* Ap = A + (size_t)(rowBase + row) * Dm + kh;
    const float* Bp = W + (size_t)(colBase + row) * Dm + kh;

    float c[4][4][4];
#pragma unroll
    for (int a = 0; a < 4; a++)
#pragma unroll
        for (int b = 0; b < 4; b++)
#pragma unroll
            for (int d = 0; d < 4; d++) c[a][b][d] = 0.f;

    float4 ra[4], rb[4];
#pragma unroll
    for (int i = 0; i < 4; i++) {
        ra[i] = *(const float4*)(Ap + i * 4);
        rb[i] = *(const float4*)(Bp + i * 4);
    }

    auto stsStage = [&](int buf) {
        uint32_t* As = smg + buf * STAGE;
        uint32_t* Bs = As + HALF;
        uint32_t* pa = As + row * SKS + kh;
        uint32_t* pb = Bs + row * SKS + kh;
#pragma unroll
        for (int i = 0; i < 4; i++) {
            pa[i * 4 + 0] = f2tf32(ra[i].x); pa[i * 4 + 1] = f2tf32(ra[i].y);
            pa[i * 4 + 2] = f2tf32(ra[i].z); pa[i * 4 + 3] = f2tf32(ra[i].w);
            pb[i * 4 + 0] = f2tf32(rb[i].x); pb[i * 4 + 1] = f2tf32(rb[i].y);
            pb[i * 4 + 2] = f2tf32(rb[i].z); pb[i * 4 + 3] = f2tf32(rb[i].w);
        }
    };

    stsStage(0);
    __syncthreads();

    for (int s = 0; s < NSTAGE; s++) {
        if (s + 1 < NSTAGE) {
#pragma unroll
            for (int i = 0; i < 4; i++) {
                ra[i] = *(const float4*)(Ap + (s + 1) * BK + i * 4);
                rb[i] = *(const float4*)(Bp + (s + 1) * BK + i * 4);
            }
        }
        const uint32_t* As = smg + (s & 1) * STAGE;
        const uint32_t* Bs = As + HALF;
        const uint32_t* abase = As + (warpM * 64 + lq) * SKS + lr;
        const uint32_t* bbase = Bs + (warpN * 32 + lq) * SKS + lr;
#pragma unroll
        for (int kk = 0; kk < BK; kk += 8) {
            uint32_t af[4][4];
#pragma unroll
            for (int mt = 0; mt < 4; mt++) {
                const uint32_t* p = abase + mt * 16 * SKS + kk;
                af[mt][0] = p[0];
                af[mt][1] = p[8 * SKS];
                af[mt][2] = p[4];
                af[mt][3] = p[8 * SKS + 4];
            }
            uint32_t bf[4][2];
#pragma unroll
            for (int nt = 0; nt < 4; nt++) {
                const uint32_t* p = bbase + nt * 8 * SKS + kk;
                bf[nt][0] = p[0];
                bf[nt][1] = p[4];
            }
#pragma unroll
            for (int mt = 0; mt < 4; mt++)
#pragma unroll
                for (int nt = 0; nt < 4; nt++)
                    mma8(c[mt][nt], af[mt], bf[nt]);
        }
        if (s + 1 < NSTAGE) {
            stsStage((s + 1) & 1);
            __syncthreads();
        }
    }

    // Epilogue. C frag (mt,nt): rows r0 = lane/4 (+8), cols (lane%4)*2 (+1)
#pragma unroll
    for (int mt = 0; mt < 4; mt++) {
        const int r0 = rowBase + warpM * 64 + mt * 16 + lq;
#pragma unroll
        for (int nt = 0; nt < 4; nt++) {
            const int n = colBase + warpN * 32 + nt * 8 + (lr << 1);
            float bx = bias[n], by = bias[n + 1];
#pragma unroll
            for (int half = 0; half < 2; half++) {
                const int m = r0 + half * 8;
                float2 v;
                v.x = (c[mt][nt][half * 2 + 0] + bx) * scale;
                v.y = (c[mt][nt][half * 2 + 1] + by) * scale;
                if (MODE == 0) {
                    const int b_ = m >> 11, s_ = m & 2047, h_ = n >> 6;
                    *(float2*)(out + ((size_t)(b_ * Hh + h_) * Sq + s_) * Dh + (n & 63)) = v;
                } else {
                    *(float2*)(out + (size_t)m * Dm + n) = v;
                }
            }
        }
    }
}

__global__ __launch_bounds__(256) void proj_mma(
    const float* __restrict__ X,
    const float* __restrict__ Wq, const float* __restrict__ bq,
    const float* __restrict__ Wk, const float* __restrict__ bk,
    const float* __restrict__ Wv, const float* __restrict__ bv)
{
    const int z = blockIdx.z;
    const float* W    = (z == 0) ? Wq : (z == 1) ? Wk : Wv;
    const float* bias = (z == 0) ? bq : (z == 1) ? bk : bv;
    float* out        = (z == 0) ? g_q : (z == 1) ? g_k : g_v;
    const float scale = (z == 0) ? 0.125f : 1.0f;
    gemm_core<0>(X, W, bias, scale, out, blockIdx.y * BM, blockIdx.x * BN);
}

__global__ __launch_bounds__(256) void outproj_mma(float* __restrict__ Out)
{
    gemm_core<1>(g_attn, g_Weff, g_beff, 1.0f, Out, blockIdx.y * BM, blockIdx.x * BN);
}

// ===================== flash attention via mma.sync tf32 =====================
// BQ=128 (8 warps x m16), BKV=64, DH=64. tf32 tiles in smem.
constexpr int AQS = 68;                           // padded stride (uints)
constexpr int AT_Q = 128 * AQS;
constexpr int AT_K = 64 * AQS;
constexpr int AT_V = 64 * AQS;
constexpr int AT_P = 128 * AQS;
constexpr int AT_DYN = (AT_Q + AT_K + AT_V + AT_P) * 4;   // 104448 B

__global__ __launch_bounds__(256) void attn_mma()
{
    extern __shared__ uint32_t sma[];
    uint32_t* Qs = sma;
    uint32_t* Ks = Qs + AT_Q;
    uint32_t* Vs = Ks + AT_K;
    uint32_t* Ps = Vs + AT_V;

    const int tid = threadIdx.x, wid = tid >> 5, lane = tid & 31;
    const int lq = lane >> 2, lr = lane & 3;
    const int qt = gridDim.x - 1 - blockIdx.x;    // big tiles first
    const int bh = blockIdx.y;
    const int qbase = qt * 128;
    const int wr0 = wid * 16;                     // warp's local q-row base

    // Load Q tile [128 x 64] -> tf32 smem
    {
        const float* Qg = g_q + ((size_t)bh * Sq + qbase) * Dh;
        const int r = tid >> 1, c0 = (tid & 1) * 32;
#pragma unroll
        for (int i = 0; i < 8; i++) {
            float4 v = *(const float4*)(Qg + r * Dh + c0 + i * 4);
            uint32_t* p = Qs + r * AQS + c0 + i * 4;
            p[0] = f2tf32(v.x); p[1] = f2tf32(v.y); p[2] = f2tf32(v.z); p[3] = f2tf32(v.w);
        }
    }

    float m0 = -1e30f, m1 = -1e30f, l0 = 0.f, l1 = 0.f;
    float o[8][4];
#pragma unroll
    for (int nt = 0; nt < 8; nt++)
#pragma unroll
        for (int d = 0; d < 4; d++) o[nt][d] = 0.f;

    const int ktmax = 2 * qt + 1;
    for (int kt = 0; kt <= ktmax; kt++) {
        __syncthreads();                           // prev K/V fully consumed
        {
            const float* Kg = g_k + ((size_t)bh * Sq + kt * 64) * Dh;
            const float* Vg = g_v + ((size_t)bh * Sq + kt * 64) * Dh;
            const int r = tid >> 2, c0 = (tid & 3) * 16;
#pragma unroll
            for (int i = 0; i < 4; i++) {
                float4 kv = *(const float4*)(Kg + r * Dh + c0 + i * 4);
                float4 vv = *(const float4*)(Vg + r * Dh + c0 + i * 4);
                uint32_t* pk = Ks + r * AQS + c0 + i * 4;
                uint32_t* pv = Vs + r * AQS + c0 + i * 4;
                pk[0] = f2tf32(kv.x); pk[1] = f2tf32(kv.y); pk[2] = f2tf32(kv.z); pk[3] = f2tf32(kv.w);
                pv[0] = f2tf32(vv.x); pv[1] = f2tf32(vv.y); pv[2] = f2tf32(vv.z); pv[3] = f2tf32(vv.w);
            }
        }
        __syncthreads();

        const int kvbase = kt * 64;
        if (kvbase > qbase + wr0 + 15) continue;   // warp fully masked

        // S = Q K^T for this warp's 16 rows
        float sc[8][4];
#pragma unroll
        for (int nt = 0; nt < 8; nt++)
#pragma unroll
            for (int d = 0; d < 4; d++) sc[nt][d] = 0.f;

        const uint32_t* qb = Qs + (wr0 + lq) * AQS + lr;
        const uint32_t* kb = Ks + lq * AQS + lr;
#pragma unroll
        for (int kk = 0; kk < 64; kk += 8) {
            uint32_t af[4];
            af[0] = qb[kk];
            af[1] = qb[8 * AQS + kk];
            af[2] = qb[kk + 4];
            af[3] = qb[8 * AQS + kk + 4];
#pragma unroll
            for (int nt = 0; nt < 8; nt++) {
                uint32_t bf[2];
                bf[0] = kb[nt * 8 * AQS + kk];
                bf[1] = kb[nt * 8 * AQS + kk + 4];
                mma8(sc[nt], af, bf);
            }
        }

        // causal mask (only near the diagonal)
        const int row0 = qbase + wr0 + lq, row1 = row0 + 8;
        if (kvbase + 63 > row0) {
#pragma unroll
            for (int nt = 0; nt < 8; nt++) {
                const int cg = kvbase + nt * 8 + (lr << 1);
                if (cg > row0)     sc[nt][0] = -1e30f;
                if (cg + 1 > row0) sc[nt][1] = -1e30f;
                if (cg > row1)     sc[nt][2] = -1e30f;
                if (cg + 1 > row1) sc[nt][3] = -1e30f;
            }
        }

        // online softmax (rows row0, row1); quad lanes share rows
        float mx0 = -1e30f, mx1 = -1e30f;
#pragma unroll
        for (int nt = 0; nt < 8; nt++) {
            mx0 = fmaxf(mx0, fmaxf(sc[nt][0], sc[nt][1]));
            mx1 = fmaxf(mx1, fmaxf(sc[nt][2], sc[nt][3]));
        }
        mx0 = fmaxf(mx0, __shfl_xor_sync(0xffffffffu, mx0, 1));
        mx0 = fmaxf(mx0, __shfl_xor_sync(0xffffffffu, mx0, 2));
        mx1 = fmaxf(mx1, __shfl_xor_sync(0xffffffffu, mx1, 1));
        mx1 = fmaxf(mx1, __shfl_xor_sync(0xffffffffu, mx1, 2));
        const float mn0 = fmaxf(m0, mx0), mn1 = fmaxf(m1, mx1);
        const float cr0 = __expf(m0 - mn0), cr1 = __expf(m1 - mn1);
        float s0 = 0.f, s1 = 0.f;
#pragma unroll
        for (int nt = 0; nt < 8; nt++) {
            sc[nt][0] = __expf(sc[nt][0] - mn0); s0 += sc[nt][0];
            sc[nt][1] = __expf(sc[nt][1] - mn0); s0 += sc[nt][1];
            sc[nt][2] = __expf(sc[nt][2] - mn1); s1 += sc[nt][2];
            sc[nt][3] = __expf(sc[nt][3] - mn1); s1 += sc[nt][3];
        }
        s0 += __shfl_xor_sync(0xffffffffu, s0, 1);
        s0 += __shfl_xor_sync(0xffffffffu, s0, 2);
        s1 += __shfl_xor_sync(0xffffffffu, s1, 1);
        s1 += __shfl_xor_sync(0xffffffffu, s1, 2);
        l0 = l0 * cr0 + s0; m0 = mn0;
        l1 = l1 * cr1 + s1; m1 = mn1;
#pragma unroll
        for (int nt = 0; nt < 8; nt++) {
            o[nt][0] *= cr0; o[nt][1] *= cr0;
            o[nt][2] *= cr1; o[nt][3] *= cr1;
        }

        // P -> per-warp smem (tf32), then O += P V
        __syncwarp();                              // prior PV reads done
        uint32_t* pp0 = Ps + (wr0 + lq) * AQS + (lr << 1);
        uint32_t* pp1 = pp0 + 8 * AQS;
#pragma unroll
        for (int nt = 0; nt < 8; nt++) {
            pp0[nt * 8 + 0] = f2tf32(sc[nt][0]);
            pp0[nt * 8 + 1] = f2tf32(sc[nt][1]);
            pp1[nt * 8 + 0] = f2tf32(sc[nt][2]);
            pp1[nt * 8 + 1] = f2tf32(sc[nt][3]);
        }
        __syncwarp();

        const uint32_t* pb = Ps + (wr0 + lq) * AQS + lr;
        const uint32_t* vb = Vs + lr * AQS + lq;
#pragma unroll
        for (int kk = 0; kk < 64; kk += 8) {
            uint32_t af[4];
            af[0] = pb[kk];
            af[1] = pb[8 * AQS + kk];
            af[2] = pb[kk + 4];
            af[3] = pb[8 * AQS + kk + 4];
#pragma unroll
            for (int nt = 0; nt < 8; nt++) {
                uint32_t bf[2];
                bf[0] = vb[kk * AQS + nt * 8];
                bf[1] = vb[(kk + 4) * AQS + nt * 8];
                mma8(o[nt], af, bf);
            }
        }
    }

    // write O / l
    const int b_ = bh >> 4, h_ = bh & 15;
    const int r0g = qbase + wr0 + lq, r1g = r0g + 8;
    const float i0 = 1.0f / l0, i1 = 1.0f / l1;
#pragma unroll
    for (int nt = 0; nt < 8; nt++) {
        const int col = h_ * Dh + nt * 8 + (lr << 1);
        float2 v0 = {o[nt][0] * i0, o[nt][1] * i0};
        float2 v1 = {o[nt][2] * i1, o[nt][3] * i1};
        *(float2*)(g_attn + ((size_t)b_ * Sq + r0g) * Dm + col) = v0;
        *(float2*)(g_attn + ((size_t)b_ * Sq + r1g) * Dm + col) = v1;
    }
}

// ===================== launch =====================
extern "C" void kernel_launch(void* const* d_in, const int* in_sizes, int n_in,
                              void* d_out, int out_size) {
    const float* x    = (const float*)d_in[0];
    const float* w    = (const float*)d_in[1];
    const float* Wq   = (const float*)d_in[2];
    const float* bq   = (const float*)d_in[3];
    const float* Wk   = (const float*)d_in[4];
    const float* bk   = (const float*)d_in[5];
    const float* Wv   = (const float*)d_in[6];
    const float* bv   = (const float*)d_in[7];
    const float* Wout = (const float*)d_in[8];
    const float* bout = (const float*)d_in[9];
    float* out = (float*)d_out;

    combine_kernel<<<(Dm * Dm + 255) / 256, 256>>>(w, Wout, bout);

    cudaFuncSetAttribute(proj_mma, cudaFuncAttributeMaxDynamicSharedMemorySize, GEMM_DYN);
    proj_mma<<<dim3(Dm / BN, Mrows / BM, 3), 256, GEMM_DYN>>>(x, Wq, bq, Wk, bk, Wv, bv);

    cudaFuncSetAttribute(attn_mma, cudaFuncAttributeMaxDynamicSharedMemorySize, AT_DYN);
    attn_mma<<<dim3(Sq / 128, Bb * Hh), 256, AT_DYN>>>();

    cudaFuncSetAttribute(outproj_mma, cudaFuncAttributeMaxDynamicSharedMemorySize, GEMM_DYN);
    outproj_mma<<<dim3(Dm / BN, Mrows / BM), 256, GEMM_DYN>>>(out);
}

// round 5
// speedup vs baseline: 2.8764x; 1.0523x over previous
#include <cuda_runtime.h>
#include <cstdint>

// Problem constants
constexpr int Bb = 2, Sq = 2048, Dm = 1024, Hh = 16, Dh = 64;
constexpr int Mrows = Bb * Sq; // 4096

// Scratch (no cudaMalloc allowed)
__device__ float g_q[Bb * Hh * Sq * Dh];     // [B,H,S,DH], tf32-rounded, Q pre-scaled by 1/8
__device__ float g_k[Bb * Hh * Sq * Dh];
__device__ float g_v[Bb * Hh * Sq * Dh];
__device__ float g_attn[Bb * Sq * Dm];       // tf32-rounded
__device__ float g_Weff[Dm * Dm];            // tf32-rounded
__device__ float g_beff[Dm];                 // fp32
__device__ float g_xt[Bb * Sq * Dm];         // tf32-rounded x
__device__ float g_wqt[Dm * Dm];             // tf32-rounded weights
__device__ float g_wkt[Dm * Dm];
__device__ float g_wvt[Dm * Dm];

// ===================== helpers =====================
__device__ __forceinline__ uint32_t f2tf32(float f) {
    uint32_t r;
    asm("cvt.rna.tf32.f32 %0, %1;" : "=r"(r) : "f"(f));
    return r;
}
__device__ __forceinline__ float tf32r(float f) { return __uint_as_float(f2tf32(f)); }
__device__ __forceinline__ uint32_t smem_u32(const void* p) {
    uint32_t a;
    asm("{ .reg .u64 t; cvta.to.shared.u64 t, %1; cvt.u32.u64 %0, t; }" : "=r"(a) : "l"(p));
    return a;
}
__device__ __forceinline__ void cpa16(uint32_t d, const void* s) {
    asm volatile("cp.async.cg.shared.global [%0], [%1], 16;" :: "r"(d), "l"(s));
}
__device__ __forceinline__ void cpa_commit() {
    asm volatile("cp.async.commit_group;" ::: "memory");
}
template <int N>
__device__ __forceinline__ void cpa_wait() {
    asm volatile("cp.async.wait_group %0;" :: "n"(N) : "memory");
}
// D = A(16x8, tf32) * B(8x8, tf32) + D, fp32 accum
__device__ __forceinline__ void mma8(float* c, const uint32_t* a, const uint32_t* b) {
    asm volatile(
        "mma.sync.aligned.m16n8k8.row.col.f32.tf32.tf32.f32 "
        "{%0,%1,%2,%3}, {%4,%5,%6,%7}, {%8,%9}, {%0,%1,%2,%3};"
        : "+f"(c[0]), "+f"(c[1]), "+f"(c[2]), "+f"(c[3])
        : "r"(a[0]), "r"(a[1]), "r"(a[2]), "r"(a[3]), "r"(b[0]), "r"(b[1]));
}

// ===================== prep: conversions + Weff combine =====================
__global__ void prep_kernel(const float* __restrict__ w,  const float* __restrict__ x,
                            const float* __restrict__ Wq, const float* __restrict__ Wk,
                            const float* __restrict__ Wv, const float* __restrict__ Wout,
                            const float* __restrict__ bout) {
    const float w0 = w[0], w1 = w[1], w2 = w[2], w3 = w[3];
    for (int i = blockIdx.x * blockDim.x + threadIdx.x; i < Mrows * Dm;
         i += gridDim.x * blockDim.x) {
        g_xt[i] = tf32r(x[i]);
        if (i < Dm * Dm) {
            g_wqt[i] = tf32r(Wq[i]);
            g_wkt[i] = tf32r(Wk[i]);
            g_wvt[i] = tf32r(Wv[i]);
            g_Weff[i] = tf32r(w0 * Wout[i] + w1 * Wout[i + Dm * Dm]
                            + w2 * Wout[i + 2 * Dm * Dm] + w3 * Wout[i + 3 * Dm * Dm]);
        }
        if (i < Dm) {
            g_beff[i] = w0 * bout[i] + w1 * bout[i + Dm]
                      + w2 * bout[i + 2 * Dm] + w3 * bout[i + 3 * Dm];
        }
    }
}

// ===================== tf32 NT GEMM, 3-stage cp.async pipeline =====================
// 128x128 CTA tile, 8 warps (warp tile 64x32), BK=32.
constexpr int BM = 128, BN = 128, BK = 32;
constexpr int SKS = BK + 4;                     // padded stride (uints); 144B = 16B-aligned
constexpr int TILEU = BM * SKS;                 // uints per matrix tile
constexpr int STAGEU = 2 * TILEU;               // A+B
constexpr int NST = 3;
constexpr int GEMM_DYN = NST * STAGEU * 4;      // 110592 B
constexpr int NSTAGE = Dm / BK;                 // 32

template <int MODE>  // 0 = head-split QKV epilogue (tf32-rounded out), 1 = plain fp32
__device__ __forceinline__ void gemm_core(
    const float* __restrict__ A, const float* __restrict__ W,
    const float* __restrict__ bias, float scale, float* __restrict__ out,
    int rowBase, int colBase)
{
    extern __shared__ uint32_t smg[];
    const uint32_t smb = smem_u32(smg);
    const int tid = threadIdx.x, wid = tid >> 5, lane = tid & 31;
    const int lq = lane >> 2, lr = lane & 3;
    const int warpM = wid & 1, warpN = wid >> 1;       // 2 x 4 warps

    // load mapping: 2 threads per row, 16 floats (4x16B) each per matrix
    const int row = tid >> 1;
    const int kh = (tid & 1) << 4;
    const float* Ap = A + (size_t)(rowBase + row) * Dm + kh;
    const float* Bp = W + (size_t)(colBase + row) * Dm + kh;
    const uint32_t sa0 = smb + (uint32_t)(row * SKS + kh) * 4;

    auto issue = [&](int s) {
        const int buf = s % NST;
        const uint32_t sa = sa0 + (uint32_t)(buf * STAGEU) * 4;
        const uint32_t sb = sa + (uint32_t)TILEU * 4;
        const float* ga = Ap + s * BK;
        const float* gb = Bp + s * BK;
#pragma unroll
        for (int i = 0; i < 4; i++) {
            cpa16(sa + i * 16, ga + i * 4);
            cpa16(sb + i * 16, gb + i * 4);
        }
        cpa_commit();
    };

    float c[4][4][4];
#pragma unroll
    for (int a = 0; a < 4; a++)
#pragma unroll
        for (int b = 0; b < 4; b++)
#pragma unroll
            for (int d = 0; d < 4; d++) c[a][b][d] = 0.f;

    issue(0); issue(1); issue(2);

    for (int s = 0; s < NSTAGE; s++) {
        if (s < NSTAGE - 2) cpa_wait<2>(); else cpa_wait<0>();
        __syncthreads();

        const uint32_t* As = smg + (s % NST) * STAGEU;
        const uint32_t* Bs = As + TILEU;
        const uint32_t* abase = As + (warpM * 64 + lq) * SKS + lr;
        const uint32_t* bbase = Bs + (warpN * 32 + lq) * SKS + lr;
#pragma unroll
        for (int kk = 0; kk < BK; kk += 8) {
            uint32_t af[4][4];
#pragma unroll
            for (int mt = 0; mt < 4; mt++) {
                const uint32_t* p = abase + mt * 16 * SKS + kk;
                af[mt][0] = p[0];
                af[mt][1] = p[8 * SKS];
                af[mt][2] = p[4];
                af[mt][3] = p[8 * SKS + 4];
            }
            uint32_t bf[4][2];
#pragma unroll
            for (int nt = 0; nt < 4; nt++) {
                const uint32_t* p = bbase + nt * 8 * SKS + kk;
                bf[nt][0] = p[0];
                bf[nt][1] = p[4];
            }
#pragma unroll
            for (int mt = 0; mt < 4; mt++)
#pragma unroll
                for (int nt = 0; nt < 4; nt++)
                    mma8(c[mt][nt], af[mt], bf[nt]);
        }
        __syncthreads();
        if (s + NST < NSTAGE) issue(s + NST);
    }

    // Epilogue. C frag (mt,nt): rows lq (+8), cols (lane%4)*2 (+1)
#pragma unroll
    for (int mt = 0; mt < 4; mt++) {
        const int r0 = rowBase + warpM * 64 + mt * 16 + lq;
#pragma unroll
        for (int nt = 0; nt < 4; nt++) {
            const int n = colBase + warpN * 32 + nt * 8 + (lr << 1);
            float bx = bias[n], by = bias[n + 1];
#pragma unroll
            for (int half = 0; half < 2; half++) {
                const int m = r0 + half * 8;
                float2 v;
                v.x = (c[mt][nt][half * 2 + 0] + bx) * scale;
                v.y = (c[mt][nt][half * 2 + 1] + by) * scale;
                if (MODE == 0) {
                    v.x = tf32r(v.x); v.y = tf32r(v.y);
                    const int b_ = m >> 11, s_ = m & 2047, h_ = n >> 6;
                    *(float2*)(out + ((size_t)(b_ * Hh + h_) * Sq + s_) * Dh + (n & 63)) = v;
                } else {
                    *(float2*)(out + (size_t)m * Dm + n) = v;
                }
            }
        }
    }
}

__global__ __launch_bounds__(256, 2) void proj_mma(
    const float* __restrict__ bq, const float* __restrict__ bk, const float* __restrict__ bv)
{
    const int z = blockIdx.z;
    const float* W    = (z == 0) ? g_wqt : (z == 1) ? g_wkt : g_wvt;
    const float* bias = (z == 0) ? bq : (z == 1) ? bk : bv;
    float* out        = (z == 0) ? g_q : (z == 1) ? g_k : g_v;
    const float scale = (z == 0) ? 0.125f : 1.0f;
    gemm_core<0>(g_xt, W, bias, scale, out, blockIdx.y * BM, blockIdx.x * BN);
}

__global__ __launch_bounds__(256, 2) void outproj_mma(float* __restrict__ Out)
{
    gemm_core<1>(g_attn, g_Weff, g_beff, 1.0f, Out, blockIdx.y * BM, blockIdx.x * BN);
}

// ===================== flash attention, cp.async K/V double buffer =====================
// BQ=128 (8 warps x m16), BKV=64, DH=64.
constexpr int AQS = 68;                           // padded stride (uints); 272B 16B-aligned
constexpr int AT_Q = 128 * AQS;
constexpr int AT_KV = 64 * AQS;                   // one K or V tile
constexpr int AT_DYN = (AT_Q + 4 * AT_KV + 128 * AQS) * 4;   // Q + K0 V0 K1 V1 + P

__global__ __launch_bounds__(256) void attn_mma()
{
    extern __shared__ uint32_t sma[];
    uint32_t* Qs = sma;
    uint32_t* Ps = sma + AT_Q + 4 * AT_KV;
    const uint32_t smb = smem_u32(sma);

    const int tid = threadIdx.x, wid = tid >> 5, lane = tid & 31;
    const int lq = lane >> 2, lr = lane & 3;
    const int qt = gridDim.x - 1 - blockIdx.x;    // big tiles first
    const int bh = blockIdx.y;
    const int qbase = qt * 128;
    const int wr0 = wid * 16;                     // warp's local q-row base

    const float* Kg0 = g_k + (size_t)bh * Sq * Dh;
    const float* Vg0 = g_v + (size_t)bh * Sq * Dh;

    // K/V loader mapping: 4 threads per row, 16 floats each
    const int r2 = tid >> 2, c2 = (tid & 3) << 4;
    const uint32_t kvso = (uint32_t)(r2 * AQS + c2) * 4;

    auto issueKV = [&](int kt, int buf) {
        const uint32_t kb = smb + (uint32_t)(AT_Q + 2 * buf * AT_KV) * 4 + kvso;
        const uint32_t vb = kb + (uint32_t)AT_KV * 4;
        const float* kp = Kg0 + (size_t)(kt * 64 + r2) * Dh + c2;
        const float* vp = Vg0 + (size_t)(kt * 64 + r2) * Dh + c2;
#pragma unroll
        for (int i = 0; i < 4; i++) {
            cpa16(kb + i * 16, kp + i * 4);
            cpa16(vb + i * 16, vp + i * 4);
        }
        cpa_commit();
    };

    // Q tile [128x64] via cp.async (group 0, shared with KV0)
    {
        const float* Qg = g_q + ((size_t)bh * Sq + qbase) * Dh;
        const int r = tid >> 1, c0 = (tid & 1) << 5;
        const uint32_t qa = smb + (uint32_t)(r * AQS + c0) * 4;
        const float* qp = Qg + (size_t)r * Dh + c0;
#pragma unroll
        for (int i = 0; i < 8; i++) cpa16(qa + i * 16, qp + i * 4);
    }
    issueKV(0, 0);   // commits Q+KV0 as one group

    float m0 = -1e30f, m1 = -1e30f, l0 = 0.f, l1 = 0.f;
    float o[8][4];
#pragma unroll
    for (int nt = 0; nt < 8; nt++)
#pragma unroll
        for (int d = 0; d < 4; d++) o[nt][d] = 0.f;

    const int ktmax = 2 * qt + 1;
    for (int kt = 0; kt <= ktmax; kt++) {
        if (kt < ktmax) { issueKV(kt + 1, (kt + 1) & 1); cpa_wait<1>(); }
        else            { cpa_wait<0>(); }
        __syncthreads();

        const int kvbase = kt * 64;
        if (kvbase <= qbase + wr0 + 15) {           // warp not fully masked
            const uint32_t* Ks = sma + AT_Q + 2 * (kt & 1) * AT_KV;
            const uint32_t* Vs = Ks + AT_KV;

            // S = Q K^T
            float sc[8][4];
#pragma unroll
            for (int nt = 0; nt < 8; nt++)
#pragma unroll
                for (int d = 0; d < 4; d++) sc[nt][d] = 0.f;

            const uint32_t* qb = Qs + (wr0 + lq) * AQS + lr;
            const uint32_t* kb = Ks + lq * AQS + lr;
#pragma unroll
            for (int kk = 0; kk < 64; kk += 8) {
                uint32_t af[4];
                af[0] = qb[kk];
                af[1] = qb[8 * AQS + kk];
                af[2] = qb[kk + 4];
                af[3] = qb[8 * AQS + kk + 4];
#pragma unroll
                for (int nt = 0; nt < 8; nt++) {
                    uint32_t bf[2];
                    bf[0] = kb[nt * 8 * AQS + kk];
                    bf[1] = kb[nt * 8 * AQS + kk + 4];
                    mma8(sc[nt], af, bf);
                }
            }

            // causal mask
            const int row0 = qbase + wr0 + lq, row1 = row0 + 8;
            if (kvbase + 63 > row0) {
#pragma unroll
                for (int nt = 0; nt < 8; nt++) {
                    const int cg = kvbase + nt * 8 + (lr << 1);
                    if (cg > row0)     sc[nt][0] = -1e30f;
                    if (cg + 1 > row0) sc[nt][1] = -1e30f;
                    if (cg > row1)     sc[nt][2] = -1e30f;
                    if (cg + 1 > row1) sc[nt][3] = -1e30f;
                }
            }

            // online softmax (rows row0, row1)
            float mx0 = -1e30f, mx1 = -1e30f;
#pragma unroll
            for (int nt = 0; nt < 8; nt++) {
                mx0 = fmaxf(mx0, fmaxf(sc[nt][0], sc[nt][1]));
                mx1 = fmaxf(mx1, fmaxf(sc[nt][2], sc[nt][3]));
            }
            mx0 = fmaxf(mx0, __shfl_xor_sync(0xffffffffu, mx0, 1));
            mx0 = fmaxf(mx0, __shfl_xor_sync(0xffffffffu, mx0, 2));
            mx1 = fmaxf(mx1, __shfl_xor_sync(0xffffffffu, mx1, 1));
            mx1 = fmaxf(mx1, __shfl_xor_sync(0xffffffffu, mx1, 2));
            const float mn0 = fmaxf(m0, mx0), mn1 = fmaxf(m1, mx1);
            const float cr0 = __expf(m0 - mn0), cr1 = __expf(m1 - mn1);
            float s0 = 0.f, s1 = 0.f;
#pragma unroll
            for (int nt = 0; nt < 8; nt++) {
                sc[nt][0] = __expf(sc[nt][0] - mn0); s0 += sc[nt][0];
                sc[nt][1] = __expf(sc[nt][1] - mn0); s0 += sc[nt][1];
                sc[nt][2] = __expf(sc[nt][2] - mn1); s1 += sc[nt][2];
                sc[nt][3] = __expf(sc[nt][3] - mn1); s1 += sc[nt][3];
            }
            s0 += __shfl_xor_sync(0xffffffffu, s0, 1);
            s0 += __shfl_xor_sync(0xffffffffu, s0, 2);
            s1 += __shfl_xor_sync(0xffffffffu, s1, 1);
            s1 += __shfl_xor_sync(0xffffffffu, s1, 2);
            l0 = l0 * cr0 + s0; m0 = mn0;
            l1 = l1 * cr1 + s1; m1 = mn1;
#pragma unroll
            for (int nt = 0; nt < 8; nt++) {
                o[nt][0] *= cr0; o[nt][1] *= cr0;
                o[nt][2] *= cr1; o[nt][3] *= cr1;
            }

            // P -> per-warp smem (tf32), then O += P V
            __syncwarp();
            uint32_t* pp0 = Ps + (wr0 + lq) * AQS + (lr << 1);
            uint32_t* pp1 = pp0 + 8 * AQS;
#pragma unroll
            for (int nt = 0; nt < 8; nt++) {
                pp0[nt * 8 + 0] = f2tf32(sc[nt][0]);
                pp0[nt * 8 + 1] = f2tf32(sc[nt][1]);
                pp1[nt * 8 + 0] = f2tf32(sc[nt][2]);
                pp1[nt * 8 + 1] = f2tf32(sc[nt][3]);
            }
            __syncwarp();

            const uint32_t* pb = Ps + (wr0 + lq) * AQS + lr;
            const uint32_t* vb = Vs + lr * AQS + lq;
#pragma unroll
            for (int kk = 0; kk < 64; kk += 8) {
                uint32_t af[4];
                af[0] = pb[kk];
                af[1] = pb[8 * AQS + kk];
                af[2] = pb[kk + 4];
                af[3] = pb[8 * AQS + kk + 4];
#pragma unroll
                for (int nt = 0; nt < 8; nt++) {
                    uint32_t bf[2];
                    bf[0] = vb[kk * AQS + nt * 8];
                    bf[1] = vb[(kk + 4) * AQS + nt * 8];
                    mma8(o[nt], af, bf);
                }
            }
        }
        __syncthreads();
    }

    // write O (tf32-rounded for outproj)
    const int b_ = bh >> 4, h_ = bh & 15;
    const int r0g = qbase + wr0 + lq, r1g = r0g + 8;
    const float i0 = 1.0f / l0, i1 = 1.0f / l1;
#pragma unroll
    for (int nt = 0; nt < 8; nt++) {
        const int col = h_ * Dh + nt * 8 + (lr << 1);
        float2 v0 = {tf32r(o[nt][0] * i0), tf32r(o[nt][1] * i0)};
        float2 v1 = {tf32r(o[nt][2] * i1), tf32r(o[nt][3] * i1)};
        *(float2*)(g_attn + ((size_t)b_ * Sq + r0g) * Dm + col) = v0;
        *(float2*)(g_attn + ((size_t)b_ * Sq + r1g) * Dm + col) = v1;
    }
}

// ===================== launch =====================
extern "C" void kernel_launch(void* const* d_in, const int* in_sizes, int n_in,
                              void* d_out, int out_size) {
    const float* x    = (const float*)d_in[0];
    const float* w    = (const float*)d_in[1];
    const float* Wq   = (const float*)d_in[2];
    const float* bq   = (const float*)d_in[3];
    const float* Wk   = (const float*)d_in[4];
    const float* bk   = (const float*)d_in[5];
    const float* Wv   = (const float*)d_in[6];
    const float* bv   = (const float*)d_in[7];
    const float* Wout = (const float*)d_in[8];
    const float* bout = (const float*)d_in[9];
    float* out = (float*)d_out;

    prep_kernel<<<8192, 512>>>(w, x, Wq, Wk, Wv, Wout, bout);

    cudaFuncSetAttribute(proj_mma, cudaFuncAttributeMaxDynamicSharedMemorySize, GEMM_DYN);
    proj_mma<<<dim3(Dm / BN, Mrows / BM, 3), 256, GEMM_DYN>>>(bq, bk, bv);

    cudaFuncSetAttribute(attn_mma, cudaFuncAttributeMaxDynamicSharedMemorySize, AT_DYN);
    attn_mma<<<dim3(Sq / 128, Bb * Hh), 256, AT_DYN>>>();

    cudaFuncSetAttribute(outproj_mma, cudaFuncAttributeMaxDynamicSharedMemorySize, GEMM_DYN);
    outproj_mma<<<dim3(Dm / BN, Mrows / BM), 256, GEMM_DYN>>>(out);
}

// round 6
// speedup vs baseline: 3.0897x; 1.0741x over previous
#include <cuda_runtime.h>
#include <cstdint>

// Problem constants
constexpr int Bb = 2, Sq = 2048, Dm = 1024, Hh = 16, Dh = 64;
constexpr int Mrows = Bb * Sq; // 4096

// Scratch (no cudaMalloc allowed)
__device__ float g_q[Bb * Hh * Sq * Dh];     // [B,H,S,DH], tf32-rounded, Q pre-scaled by 1/8
__device__ float g_k[Bb * Hh * Sq * Dh];
__device__ float g_v[Bb * Hh * Sq * Dh];
__device__ float g_attn[Bb * Sq * Dm];       // tf32-rounded
__device__ float g_Weff[Dm * Dm];            // tf32-rounded
__device__ float g_beff[Dm];                 // fp32
__device__ float g_xt[Bb * Sq * Dm];         // tf32-rounded x
__device__ float g_wcat[3 * Dm * Dm];        // tf32-rounded Wq|Wk|Wv
__device__ float g_bcat[3 * Dm];             // bq|bk|bv

// ===================== helpers =====================
__device__ __forceinline__ uint32_t f2tf32(float f) {
    uint32_t r;
    asm("cvt.rna.tf32.f32 %0, %1;" : "=r"(r) : "f"(f));
    return r;
}
__device__ __forceinline__ float tf32r(float f) { return __uint_as_float(f2tf32(f)); }
__device__ __forceinline__ float4 tf32r4(float4 v) {
    return make_float4(tf32r(v.x), tf32r(v.y), tf32r(v.z), tf32r(v.w));
}
__device__ __forceinline__ uint32_t smem_u32(const void* p) {
    uint32_t a;
    asm("{ .reg .u64 t; cvta.to.shared.u64 t, %1; cvt.u32.u64 %0, t; }" : "=r"(a) : "l"(p));
    return a;
}
__device__ __forceinline__ void cpa16(uint32_t d, const void* s) {
    asm volatile("cp.async.cg.shared.global [%0], [%1], 16;" :: "r"(d), "l"(s));
}
__device__ __forceinline__ void cpa_commit() {
    asm volatile("cp.async.commit_group;" ::: "memory");
}
template <int N>
__device__ __forceinline__ void cpa_wait() {
    asm volatile("cp.async.wait_group %0;" :: "n"(N) : "memory");
}
// D = A(16x8, tf32) * B(8x8, tf32) + D, fp32 accum
__device__ __forceinline__ void mma8(float* c, const uint32_t* a, const uint32_t* b) {
    asm volatile(
        "mma.sync.aligned.m16n8k8.row.col.f32.tf32.tf32.f32 "
        "{%0,%1,%2,%3}, {%4,%5,%6,%7}, {%8,%9}, {%0,%1,%2,%3};"
        : "+f"(c[0]), "+f"(c[1]), "+f"(c[2]), "+f"(c[3])
        : "r"(a[0]), "r"(a[1]), "r"(a[2]), "r"(a[3]), "r"(b[0]), "r"(b[1]));
}

// ===================== prep: conversions + combines (float4) =====================
__global__ void prep_kernel(const float* __restrict__ w,  const float* __restrict__ x,
                            const float* __restrict__ Wq, const float* __restrict__ Wk,
                            const float* __restrict__ Wv,
                            const float* __restrict__ bq, const float* __restrict__ bk,
                            const float* __restrict__ bv,
                            const float* __restrict__ Wout, const float* __restrict__ bout) {
    const float w0 = w[0], w1 = w[1], w2 = w[2], w3 = w[3];
    const float4* x4  = (const float4*)x;
    const float4* wq4 = (const float4*)Wq;
    const float4* wk4 = (const float4*)Wk;
    const float4* wv4 = (const float4*)Wv;
    const float4* wo4 = (const float4*)Wout;
    float4* xt4 = (float4*)g_xt;
    float4* wc4 = (float4*)g_wcat;
    float4* we4 = (float4*)g_Weff;
    constexpr int NX = Mrows * Dm / 4;       // 1048576
    constexpr int NW = Dm * Dm / 4;          // 262144
    for (int i = blockIdx.x * blockDim.x + threadIdx.x; i < NX; i += gridDim.x * blockDim.x) {
        xt4[i] = tf32r4(x4[i]);
        if (i < NW) {
            wc4[i]          = tf32r4(wq4[i]);
            wc4[i + NW]     = tf32r4(wk4[i]);
            wc4[i + 2 * NW] = tf32r4(wv4[i]);
            float4 a = wo4[i], b = wo4[i + NW], c = wo4[i + 2 * NW], d = wo4[i + 3 * NW];
            float4 e;
            e.x = w0 * a.x + w1 * b.x + w2 * c.x + w3 * d.x;
            e.y = w0 * a.y + w1 * b.y + w2 * c.y + w3 * d.y;
            e.z = w0 * a.z + w1 * b.z + w2 * c.z + w3 * d.z;
            e.w = w0 * a.w + w1 * b.w + w2 * c.w + w3 * d.w;
            we4[i] = tf32r4(e);
        }
        if (i < 3 * Dm) {
            const int z = i >> 10, j = i & 1023;
            g_bcat[i] = (z == 0) ? bq[j] : (z == 1) ? bk[j] : bv[j];
        }
        if (i < Dm) {
            g_beff[i] = w0 * bout[i] + w1 * bout[i + Dm]
                      + w2 * bout[i + 2 * Dm] + w3 * bout[i + 3 * Dm];
        }
    }
}

// ===================== tf32 NT GEMM, 256x128 tile, 512 thr, 3-stage ring =====================
constexpr int BM = 256, BN = 128, BK = 32;
constexpr int SKS = BK + 4;                     // padded stride (uints); 144B = 16B-aligned
constexpr int TILEA = BM * SKS;                 // 9216 uints
constexpr int TILEB = BN * SKS;                 // 4608 uints
constexpr int STAGEU = TILEA + TILEB;           // 13824 uints
constexpr int NST = 3;
constexpr int GEMM_DYN = NST * STAGEU * 4;      // 165888 B
constexpr int NSTAGE = Dm / BK;                 // 32

template <int MODE>  // 0 = head-split QKV epilogue (tf32-rounded out), 1 = plain fp32
__device__ __forceinline__ void gemm_core(
    const float* __restrict__ A, const float* __restrict__ W,
    const float* __restrict__ bias, float scale, float* __restrict__ out,
    int rowBase, int colBase)
{
    extern __shared__ uint32_t smg[];
    const uint32_t smb = smem_u32(smg);
    const int tid = threadIdx.x, wid = tid >> 5, lane = tid & 31;
    const int lq = lane >> 2, lr = lane & 3;
    const int warpM = wid & 3, warpN = wid >> 2;       // 4 x 4 warps, warp tile 64x32

    // Loaders: A rows 256 (2 thr/row, 16 floats), B rows 128 (4 thr/row, 8 floats)
    const int rowA = tid >> 1, khA = (tid & 1) << 4;
    const int rowB = tid >> 2, khB = (tid & 3) << 3;
    const float* Ap = A + (size_t)(rowBase + rowA) * Dm + khA;
    const float* Bp = W + (size_t)(colBase + rowB) * Dm + khB;
    const uint32_t saA = smb + (uint32_t)(rowA * SKS + khA) * 4;
    const uint32_t saB = smb + (uint32_t)(TILEA + rowB * SKS + khB) * 4;

    auto issue = [&](int s) {
        const int buf = s % NST;
        const uint32_t off = (uint32_t)(buf * STAGEU) * 4;
        const float* ga = Ap + s * BK;
        const float* gb = Bp + s * BK;
#pragma unroll
        for (int i = 0; i < 4; i++) cpa16(saA + off + i * 16, ga + i * 4);
#pragma unroll
        for (int i = 0; i < 2; i++) cpa16(saB + off + i * 16, gb + i * 4);
        cpa_commit();
    };

    float c[4][4][4];
#pragma unroll
    for (int a = 0; a < 4; a++)
#pragma unroll
        for (int b = 0; b < 4; b++)
#pragma unroll
            for (int d = 0; d < 4; d++) c[a][b][d] = 0.f;

    issue(0); issue(1);

    for (int s = 0; s < NSTAGE; s++) {
        if (s == NSTAGE - 1) cpa_wait<0>(); else cpa_wait<1>();
        __syncthreads();
        if (s + 2 < NSTAGE) issue(s + 2);

        const uint32_t* As = smg + (s % NST) * STAGEU;
        const uint32_t* Bs = As + TILEA;
        const uint32_t* abase = As + (warpM * 64 + lq) * SKS + lr;
        const uint32_t* bbase = Bs + (warpN * 32 + lq) * SKS + lr;
#pragma unroll
        for (int kk = 0; kk < BK; kk += 8) {
            uint32_t af[4][4];
#pragma unroll
            for (int mt = 0; mt < 4; mt++) {
                const uint32_t* p = abase + mt * 16 * SKS + kk;
                af[mt][0] = p[0];
                af[mt][1] = p[8 * SKS];
                af[mt][2] = p[4];
                af[mt][3] = p[8 * SKS + 4];
            }
            uint32_t bf[4][2];
#pragma unroll
            for (int nt = 0; nt < 4; nt++) {
                const uint32_t* p = bbase + nt * 8 * SKS + kk;
                bf[nt][0] = p[0];
                bf[nt][1] = p[4];
            }
#pragma unroll
            for (int mt = 0; mt < 4; mt++)
#pragma unroll
                for (int nt = 0; nt < 4; nt++)
                    mma8(c[mt][nt], af[mt], bf[nt]);
        }
    }

    // Epilogue. C frag (mt,nt): rows lq (+8), cols lr*2 (+1)
#pragma unroll
    for (int mt = 0; mt < 4; mt++) {
        const int r0 = rowBase + warpM * 64 + mt * 16 + lq;
#pragma unroll
        for (int nt = 0; nt < 4; nt++) {
            const int n = colBase + warpN * 32 + nt * 8 + (lr << 1);
            float bx = bias[n], by = bias[n + 1];
#pragma unroll
            for (int half = 0; half < 2; half++) {
                const int m = r0 + half * 8;
                float2 v;
                v.x = (c[mt][nt][half * 2 + 0] + bx) * scale;
                v.y = (c[mt][nt][half * 2 + 1] + by) * scale;
                if (MODE == 0) {
                    v.x = tf32r(v.x); v.y = tf32r(v.y);
                    const int b_ = m >> 11, s_ = m & 2047, h_ = n >> 6;
                    *(float2*)(out + ((size_t)(b_ * Hh + h_) * Sq + s_) * Dh + (n & 63)) = v;
                } else {
                    *(float2*)(out + (size_t)m * Dm + n) = v;
                }
            }
        }
    }
}

// Fused QKV projection: N = 3072 (Wq|Wk|Wv)
__global__ __launch_bounds__(512, 1) void proj_mma()
{
    const int nGlob = blockIdx.x * BN;          // 0..2944
    const int z = nGlob >> 10;                  // 0,1,2 (128 | 1024)
    const int colLocal = nGlob & 1023;
    const float* W    = g_wcat + (size_t)z * Dm * Dm;
    const float* bias = g_bcat + z * Dm;
    float* out        = (z == 0) ? g_q : (z == 1) ? g_k : g_v;
    const float scale = (z == 0) ? 0.125f : 1.0f;
    gemm_core<0>(g_xt, W, bias, scale, out, blockIdx.y * BM, colLocal);
}

__global__ __launch_bounds__(512, 1) void outproj_mma(float* __restrict__ Out)
{
    gemm_core<1>(g_attn, g_Weff, g_beff, 1.0f, Out, blockIdx.y * BM, blockIdx.x * BN);
}

// ===================== flash attention, cp.async K/V double buffer =====================
// BQ=128 (8 warps x m16), BKV=64, DH=64.
constexpr int AQS = 68;                           // padded stride (uints); 272B 16B-aligned
constexpr int AT_Q = 128 * AQS;
constexpr int AT_KV = 64 * AQS;                   // one K or V tile
constexpr int AT_DYN = (AT_Q + 4 * AT_KV + 128 * AQS) * 4;   // Q + K0 V0 K1 V1 + P

__global__ __launch_bounds__(256) void attn_mma()
{
    extern __shared__ uint32_t sma[];
    uint32_t* Qs = sma;
    uint32_t* Ps = sma + AT_Q + 4 * AT_KV;
    const uint32_t smb = smem_u32(sma);

    const int tid = threadIdx.x, wid = tid >> 5, lane = tid & 31;
    const int lq = lane >> 2, lr = lane & 3;
    const int qt = gridDim.x - 1 - blockIdx.x;    // big tiles first
    const int bh = blockIdx.y;
    const int qbase = qt * 128;
    const int wr0 = wid * 16;                     // warp's local q-row base

    const float* Kg0 = g_k + (size_t)bh * Sq * Dh;
    const float* Vg0 = g_v + (size_t)bh * Sq * Dh;

    // K/V loader mapping: 4 threads per row, 16 floats each
    const int r2 = tid >> 2, c2 = (tid & 3) << 4;
    const uint32_t kvso = (uint32_t)(r2 * AQS + c2) * 4;

    auto issueKV = [&](int kt, int buf) {
        const uint32_t kb = smb + (uint32_t)(AT_Q + 2 * buf * AT_KV) * 4 + kvso;
        const uint32_t vb = kb + (uint32_t)AT_KV * 4;
        const float* kp = Kg0 + (size_t)(kt * 64 + r2) * Dh + c2;
        const float* vp = Vg0 + (size_t)(kt * 64 + r2) * Dh + c2;
#pragma unroll
        for (int i = 0; i < 4; i++) {
            cpa16(kb + i * 16, kp + i * 4);
            cpa16(vb + i * 16, vp + i * 4);
        }
        cpa_commit();
    };

    // Q tile [128x64] via cp.async (group 0, shared with KV0)
    {
        const float* Qg = g_q + ((size_t)bh * Sq + qbase) * Dh;
        const int r = tid >> 1, c0 = (tid & 1) << 5;
        const uint32_t qa = smb + (uint32_t)(r * AQS + c0) * 4;
        const float* qp = Qg + (size_t)r * Dh + c0;
#pragma unroll
        for (int i = 0; i < 8; i++) cpa16(qa + i * 16, qp + i * 4);
    }
    issueKV(0, 0);   // commits Q+KV0 as one group

    float m0 = -1e30f, m1 = -1e30f, l0 = 0.f, l1 = 0.f;
    float o[8][4];
#pragma unroll
    for (int nt = 0; nt < 8; nt++)
#pragma unroll
        for (int d = 0; d < 4; d++) o[nt][d] = 0.f;

    const int ktmax = 2 * qt + 1;
    for (int kt = 0; kt <= ktmax; kt++) {
        if (kt < ktmax) { issueKV(kt + 1, (kt + 1) & 1); cpa_wait<1>(); }
        else            { cpa_wait<0>(); }
        __syncthreads();

        const int kvbase = kt * 64;
        if (kvbase <= qbase + wr0 + 15) {           // warp not fully masked
            const uint32_t* Ks = sma + AT_Q + 2 * (kt & 1) * AT_KV;
            const uint32_t* Vs = Ks + AT_KV;

            // S = Q K^T
            float sc[8][4];
#pragma unroll
            for (int nt = 0; nt < 8; nt++)
#pragma unroll
                for (int d = 0; d < 4; d++) sc[nt][d] = 0.f;

            const uint32_t* qb = Qs + (wr0 + lq) * AQS + lr;
            const uint32_t* kb = Ks + lq * AQS + lr;
#pragma unroll
            for (int kk = 0; kk < 64; kk += 8) {
                uint32_t af[4];
                af[0] = qb[kk];
                af[1] = qb[8 * AQS + kk];
                af[2] = qb[kk + 4];
                af[3] = qb[8 * AQS + kk + 4];
#pragma unroll
                for (int nt = 0; nt < 8; nt++) {
                    uint32_t bf[2];
                    bf[0] = kb[nt * 8 * AQS + kk];
                    bf[1] = kb[nt * 8 * AQS + kk + 4];
                    mma8(sc[nt], af, bf);
                }
            }

            // causal mask
            const int row0 = qbase + wr0 + lq, row1 = row0 + 8;
            if (kvbase + 63 > row0) {
#pragma unroll
                for (int nt = 0; nt < 8; nt++) {
                    const int cg = kvbase + nt * 8 + (lr << 1);
                    if (cg > row0)     sc[nt][0] = -1e30f;
                    if (cg + 1 > row0) sc[nt][1] = -1e30f;
                    if (cg > row1)     sc[nt][2] = -1e30f;
                    if (cg + 1 > row1) sc[nt][3] = -1e30f;
                }
            }

            // online softmax (rows row0, row1)
            float mx0 = -1e30f, mx1 = -1e30f;
#pragma unroll
            for (int nt = 0; nt < 8; nt++) {
                mx0 = fmaxf(mx0, fmaxf(sc[nt][0], sc[nt][1]));
                mx1 = fmaxf(mx1, fmaxf(sc[nt][2], sc[nt][3]));
            }
            mx0 = fmaxf(mx0, __shfl_xor_sync(0xffffffffu, mx0, 1));
            mx0 = fmaxf(mx0, __shfl_xor_sync(0xffffffffu, mx0, 2));
            mx1 = fmaxf(mx1, __shfl_xor_sync(0xffffffffu, mx1, 1));
            mx1 = fmaxf(mx1, __shfl_xor_sync(0xffffffffu, mx1, 2));
            const float mn0 = fmaxf(m0, mx0), mn1 = fmaxf(m1, mx1);
            const float cr0 = __expf(m0 - mn0), cr1 = __expf(m1 - mn1);
            float s0 = 0.f, s1 = 0.f;
#pragma unroll
            for (int nt = 0; nt < 8; nt++) {
                sc[nt][0] = __expf(sc[nt][0] - mn0); s0 += sc[nt][0];
                sc[nt][1] = __expf(sc[nt][1] - mn0); s0 += sc[nt][1];
                sc[nt][2] = __expf(sc[nt][2] - mn1); s1 += sc[nt][2];
                sc[nt][3] = __expf(sc[nt][3] - mn1); s1 += sc[nt][3];
            }
            s0 += __shfl_xor_sync(0xffffffffu, s0, 1);
            s0 += __shfl_xor_sync(0xffffffffu, s0, 2);
            s1 += __shfl_xor_sync(0xffffffffu, s1, 1);
            s1 += __shfl_xor_sync(0xffffffffu, s1, 2);
            l0 = l0 * cr0 + s0; m0 = mn0;
            l1 = l1 * cr1 + s1; m1 = mn1;
#pragma unroll
            for (int nt = 0; nt < 8; nt++) {
                o[nt][0] *= cr0; o[nt][1] *= cr0;
                o[nt][2] *= cr1; o[nt][3] *= cr1;
            }

            // P -> per-warp smem (tf32), then O += P V
            __syncwarp();
            uint32_t* pp0 = Ps + (wr0 + lq) * AQS + (lr << 1);
            uint32_t* pp1 = pp0 + 8 * AQS;
#pragma unroll
            for (int nt = 0; nt < 8; nt++) {
                pp0[nt * 8 + 0] = f2tf32(sc[nt][0]);
                pp0[nt * 8 + 1] = f2tf32(sc[nt][1]);
                pp1[nt * 8 + 0] = f2tf32(sc[nt][2]);
                pp1[nt * 8 + 1] = f2tf32(sc[nt][3]);
            }
            __syncwarp();

            const uint32_t* pb = Ps + (wr0 + lq) * AQS + lr;
            const uint32_t* vb = Vs + lr * AQS + lq;
#pragma unroll
            for (int kk = 0; kk < 64; kk += 8) {
                uint32_t af[4];
                af[0] = pb[kk];
                af[1] = pb[8 * AQS + kk];
                af[2] = pb[kk + 4];
                af[3] = pb[8 * AQS + kk + 4];
#pragma unroll
                for (int nt = 0; nt < 8; nt++) {
                    uint32_t bf[2];
                    bf[0] = vb[kk * AQS + nt * 8];
                    bf[1] = vb[(kk + 4) * AQS + nt * 8];
                    mma8(o[nt], af, bf);
                }
            }
        }
        __syncthreads();
    }

    // write O (tf32-rounded for outproj)
    const int b_ = bh >> 4, h_ = bh & 15;
    const int r0g = qbase + wr0 + lq, r1g = r0g + 8;
    const float i0 = 1.0f / l0, i1 = 1.0f / l1;
#pragma unroll
    for (int nt = 0; nt < 8; nt++) {
        const int col = h_ * Dh + nt * 8 + (lr << 1);
        float2 v0 = {tf32r(o[nt][0] * i0), tf32r(o[nt][1] * i0)};
        float2 v1 = {tf32r(o[nt][2] * i1), tf32r(o[nt][3] * i1)};
        *(float2*)(g_attn + ((size_t)b_ * Sq + r0g) * Dm + col) = v0;
        *(float2*)(g_attn + ((size_t)b_ * Sq + r1g) * Dm + col) = v1;
    }
}

// ===================== launch =====================
extern "C" void kernel_launch(void* const* d_in, const int* in_sizes, int n_in,
                              void* d_out, int out_size) {
    const float* x    = (const float*)d_in[0];
    const float* w    = (const float*)d_in[1];
    const float* Wq   = (const float*)d_in[2];
    const float* bq   = (const float*)d_in[3];
    const float* Wk   = (const float*)d_in[4];
    const float* bk   = (const float*)d_in[5];
    const float* Wv   = (const float*)d_in[6];
    const float* bv   = (const float*)d_in[7];
    const float* Wout = (const float*)d_in[8];
    const float* bout = (const float*)d_in[9];
    float* out = (float*)d_out;

    prep_kernel<<<2048, 512>>>(w, x, Wq, Wk, Wv, bq, bk, bv, Wout, bout);

    cudaFuncSetAttribute(proj_mma, cudaFuncAttributeMaxDynamicSharedMemorySize, GEMM_DYN);
    proj_mma<<<dim3(3 * Dm / BN, Mrows / BM), 512, GEMM_DYN>>>();

    cudaFuncSetAttribute(attn_mma, cudaFuncAttributeMaxDynamicSharedMemorySize, AT_DYN);
    attn_mma<<<dim3(Sq / 128, Bb * Hh), 256, AT_DYN>>>();

    cudaFuncSetAttribute(outproj_mma, cudaFuncAttributeMaxDynamicSharedMemorySize, GEMM_DYN);
    outproj_mma<<<dim3(Dm / BN, Mrows / BM), 512, GEMM_DYN>>>(out);
}

// round 8
// speedup vs baseline: 3.2351x; 1.0471x over previous
#include <cuda_runtime.h>
#include <cstdint>

// Problem constants
constexpr int Bb = 2, Sq = 2048, Dm = 1024, Hh = 16, Dh = 64;
constexpr int Mrows = Bb * Sq; // 4096

// Scratch (no cudaMalloc allowed)
__device__ float g_q[Bb * Hh * Sq * Dh];     // [B,H,S,DH], tf32-rounded, Q pre-scaled by 1/8
__device__ float g_k[Bb * Hh * Sq * Dh];
__device__ float g_v[Bb * Hh * Sq * Dh];
__device__ float g_attn[Bb * Sq * Dm];       // tf32-rounded
__device__ float g_Weff[Dm * Dm];            // tf32-rounded
__device__ float g_beff[Dm];                 // fp32
__device__ float g_xt[Bb * Sq * Dm];         // tf32-rounded x
__device__ float g_wcat[3 * Dm * Dm];        // tf32-rounded Wq|Wk|Wv
__device__ float g_bcat[3 * Dm];             // bq|bk|bv

// ===================== helpers =====================
__device__ __forceinline__ uint32_t f2tf32(float f) {
    uint32_t r;
    asm("cvt.rna.tf32.f32 %0, %1;" : "=r"(r) : "f"(f));
    return r;
}
__device__ __forceinline__ float tf32r(float f) { return __uint_as_float(f2tf32(f)); }
__device__ __forceinline__ float4 tf32r4(float4 v) {
    return make_float4(tf32r(v.x), tf32r(v.y), tf32r(v.z), tf32r(v.w));
}
__device__ __forceinline__ uint32_t smem_u32(const void* p) {
    uint32_t a;
    asm("{ .reg .u64 t; cvta.to.shared.u64 t, %1; cvt.u32.u64 %0, t; }" : "=r"(a) : "l"(p));
    return a;
}
__device__ __forceinline__ void cpa16(uint32_t d, const void* s) {
    asm volatile("cp.async.cg.shared.global [%0], [%1], 16;" :: "r"(d), "l"(s));
}
__device__ __forceinline__ void cpa_commit() {
    asm volatile("cp.async.commit_group;" ::: "memory");
}
template <int N>
__device__ __forceinline__ void cpa_wait() {
    asm volatile("cp.async.wait_group %0;" :: "n"(N) : "memory");
}
// D = A(16x8, tf32) * B(8x8, tf32) + D, fp32 accum
__device__ __forceinline__ void mma8(float* c, const uint32_t* a, const uint32_t* b) {
    asm volatile(
        "mma.sync.aligned.m16n8k8.row.col.f32.tf32.tf32.f32 "
        "{%0,%1,%2,%3}, {%4,%5,%6,%7}, {%8,%9}, {%0,%1,%2,%3};"
        : "+f"(c[0]), "+f"(c[1]), "+f"(c[2]), "+f"(c[3])
        : "r"(a[0]), "r"(a[1]), "r"(a[2]), "r"(a[3]), "r"(b[0]), "r"(b[1]));
}

// ===================== prep: conversions + combines (float4) =====================
__global__ void prep_kernel(const float* __restrict__ w,  const float* __restrict__ x,
                            const float* __restrict__ Wq, const float* __restrict__ Wk,
                            const float* __restrict__ Wv,
                            const float* __restrict__ bq, const float* __restrict__ bk,
                            const float* __restrict__ bv,
                            const float* __restrict__ Wout, const float* __restrict__ bout) {
    const float w0 = w[0], w1 = w[1], w2 = w[2], w3 = w[3];
    const float4* x4  = (const float4*)x;
    const float4* wq4 = (const float4*)Wq;
    const float4* wk4 = (const float4*)Wk;
    const float4* wv4 = (const float4*)Wv;
    const float4* wo4 = (const float4*)Wout;
    float4* xt4 = (float4*)g_xt;
    float4* wc4 = (float4*)g_wcat;
    float4* we4 = (float4*)g_Weff;
    constexpr int NX = Mrows * Dm / 4;       // 1048576
    constexpr int NW = Dm * Dm / 4;          // 262144
    for (int i = blockIdx.x * blockDim.x + threadIdx.x; i < NX; i += gridDim.x * blockDim.x) {
        xt4[i] = tf32r4(x4[i]);
        if (i < NW) {
            wc4[i]          = tf32r4(wq4[i]);
            wc4[i + NW]     = tf32r4(wk4[i]);
            wc4[i + 2 * NW] = tf32r4(wv4[i]);
            float4 a = wo4[i], b = wo4[i + NW], c = wo4[i + 2 * NW], d = wo4[i + 3 * NW];
            float4 e;
            e.x = w0 * a.x + w1 * b.x + w2 * c.x + w3 * d.x;
            e.y = w0 * a.y + w1 * b.y + w2 * c.y + w3 * d.y;
            e.z = w0 * a.z + w1 * b.z + w2 * c.z + w3 * d.z;
            e.w = w0 * a.w + w1 * b.w + w2 * c.w + w3 * d.w;
            we4[i] = tf32r4(e);
        }
        if (i < 3 * Dm) {
            const int z = i >> 10, j = i & 1023;
            g_bcat[i] = (z == 0) ? bq[j] : (z == 1) ? bk[j] : bv[j];
        }
        if (i < Dm) {
            g_beff[i] = w0 * bout[i] + w1 * bout[i + Dm]
                      + w2 * bout[i + 2 * Dm] + w3 * bout[i + 3 * Dm];
        }
    }
}

// ======== tf32 NT GEMM: CTA 256x128, 256 thr, warp tile 64x64, 4-stage ring ========
constexpr int BM = 256, BN = 128, BK = 32;
constexpr int SKS = BK + 4;                     // padded stride (uints); 144B = 16B-aligned
constexpr int TILEA = BM * SKS;                 // 9216 uints
constexpr int TILEB = BN * SKS;                 // 4608 uints
constexpr int STAGEU = TILEA + TILEB;           // 13824 uints
constexpr int NST = 4;
constexpr int GEMM_DYN = NST * STAGEU * 4;      // 221184 B
constexpr int NSTAGE = Dm / BK;                 // 32

template <int MODE>  // 0 = head-split QKV epilogue (tf32-rounded out), 1 = plain fp32
__device__ __forceinline__ void gemm_core(
    const float* __restrict__ A, const float* __restrict__ W,
    const float* __restrict__ bias, float scale, float* __restrict__ out,
    int rowBase, int colBase)
{
    extern __shared__ uint32_t smg[];
    const uint32_t smb = smem_u32(smg);
    const int tid = threadIdx.x, wid = tid >> 5, lane = tid & 31;
    const int lq = lane >> 2, lr = lane & 3;
    const int warpM = wid & 3, warpN = wid >> 2;       // 4 x 2 warps, warp tile 64x64

    // Loaders: 2 thr/row, 16 floats each. A: rows 0..127 and 128..255. B: 128 rows.
    const int rowL = tid >> 1, kh = (tid & 1) << 4;
    const float* Ap0 = A + (size_t)(rowBase + rowL) * Dm + kh;
    const float* Ap1 = Ap0 + (size_t)128 * Dm;
    const float* Bp  = W + (size_t)(colBase + rowL) * Dm + kh;
    const uint32_t saA0 = smb + (uint32_t)(rowL * SKS + kh) * 4;
    const uint32_t saA1 = saA0 + (uint32_t)(128 * SKS) * 4;
    const uint32_t saB  = smb + (uint32_t)(TILEA + rowL * SKS + kh) * 4;

    auto issue = [&](int s) {
        const uint32_t off = (uint32_t)((s % NST) * STAGEU) * 4;
        const float* ga0 = Ap0 + s * BK;
        const float* ga1 = Ap1 + s * BK;
        const float* gb  = Bp + s * BK;
#pragma unroll
        for (int i = 0; i < 4; i++) {
            cpa16(saA0 + off + i * 16, ga0 + i * 4);
            cpa16(saA1 + off + i * 16, ga1 + i * 4);
            cpa16(saB  + off + i * 16, gb  + i * 4);
        }
        cpa_commit();
    };

    float c[4][8][4];
#pragma unroll
    for (int a = 0; a < 4; a++)
#pragma unroll
        for (int b = 0; b < 8; b++)
#pragma unroll
            for (int d = 0; d < 4; d++) c[a][b][d] = 0.f;

    issue(0); issue(1); issue(2);

    for (int s = 0; s < NSTAGE; s++) {
        if (s + 2 < NSTAGE) cpa_wait<2>(); else cpa_wait<0>();
        __syncthreads();
        if (s + 3 < NSTAGE) issue(s + 3);

        const uint32_t* As = smg + (s % NST) * STAGEU;
        const uint32_t* Bs = As + TILEA;
        const uint32_t* abase = As + (warpM * 64 + lq) * SKS + lr;
        const uint32_t* bbase = Bs + (warpN * 64 + lq) * SKS + lr;
#pragma unroll
        for (int kk = 0; kk < BK; kk += 8) {
            uint32_t af[4][4];
#pragma unroll
            for (int mt = 0; mt < 4; mt++) {
                const uint32_t* p = abase + mt * 16 * SKS + kk;
                af[mt][0] = p[0];
                af[mt][1] = p[8 * SKS];
                af[mt][2] = p[4];
                af[mt][3] = p[8 * SKS + 4];
            }
            uint32_t bf[8][2];
#pragma unroll
            for (int nt = 0; nt < 8; nt++) {
                const uint32_t* p = bbase + nt * 8 * SKS + kk;
                bf[nt][0] = p[0];
                bf[nt][1] = p[4];
            }
#pragma unroll
            for (int mt = 0; mt < 4; mt++)
#pragma unroll
                for (int nt = 0; nt < 8; nt++)
                    mma8(c[mt][nt], af[mt], bf[nt]);
        }
    }

    // Epilogue. C frag (mt,nt): rows lq (+8), cols lr*2 (+1)
#pragma unroll
    for (int mt = 0; mt < 4; mt++) {
        const int r0 = rowBase + warpM * 64 + mt * 16 + lq;
#pragma unroll
        for (int nt = 0; nt < 8; nt++) {
            const int n = colBase + warpN * 64 + nt * 8 + (lr << 1);
            float bx = bias[n], by = bias[n + 1];
#pragma unroll
            for (int half = 0; half < 2; half++) {
                const int m = r0 + half * 8;
                float2 v;
                v.x = (c[mt][nt][half * 2 + 0] + bx) * scale;
                v.y = (c[mt][nt][half * 2 + 1] + by) * scale;
                if (MODE == 0) {
                    v.x = tf32r(v.x); v.y = tf32r(v.y);
                    const int b_ = m >> 11, s_ = m & 2047, h_ = n >> 6;
                    *(float2*)(out + ((size_t)(b_ * Hh + h_) * Sq + s_) * Dh + (n & 63)) = v;
                } else {
                    *(float2*)(out + (size_t)m * Dm + n) = v;
                }
            }
        }
    }
}

// Fused QKV projection: N = 3072 (Wq|Wk|Wv)
__global__ __launch_bounds__(256, 1) void proj_mma()
{
    const int nGlob = blockIdx.x * BN;          // 0..2944
    const int z = nGlob >> 10;                  // 0,1,2
    const int colLocal = nGlob & 1023;
    const float* W    = g_wcat + (size_t)z * Dm * Dm;
    const float* bias = g_bcat + z * Dm;
    float* out        = (z == 0) ? g_q : (z == 1) ? g_k : g_v;
    const float scale = (z == 0) ? 0.125f : 1.0f;
    gemm_core<0>(g_xt, W, bias, scale, out, blockIdx.y * BM, colLocal);
}

__global__ __launch_bounds__(256, 1) void outproj_mma(float* __restrict__ Out)
{
    gemm_core<1>(g_attn, g_Weff, g_beff, 1.0f, Out, blockIdx.y * BM, blockIdx.x * BN);
}

// ===================== flash attention (no P smem: quad-shuffle transpose) =====================
// BQ=128 (8 warps x m16), BKV=64, DH=64. Q + double-buffered K/V in smem.
constexpr int AQS = 68;                           // padded stride (uints); 272B 16B-aligned
constexpr int AT_Q = 128 * AQS;
constexpr int AT_KV = 64 * AQS;                   // one K or V tile
constexpr int AT_DYN = (AT_Q + 4 * AT_KV) * 4;    // 104448 B -> 2 CTAs/SM

__global__ __launch_bounds__(256, 2) void attn_mma()
{
    extern __shared__ uint32_t sma[];
    uint32_t* Qs = sma;
    const uint32_t smb = smem_u32(sma);

    const int tid = threadIdx.x, wid = tid >> 5, lane = tid & 31;
    const int lq = lane >> 2, lr = lane & 3;
    const int qt = gridDim.x - 1 - blockIdx.x;    // big tiles first
    const int bh = blockIdx.y;
    const int qbase = qt * 128;
    const int wr0 = wid * 16;                     // warp's local q-row base

    const float* Kg0 = g_k + (size_t)bh * Sq * Dh;
    const float* Vg0 = g_v + (size_t)bh * Sq * Dh;

    // K/V loader mapping: 4 threads per row, 16 floats each
    const int r2 = tid >> 2, c2 = (tid & 3) << 4;
    const uint32_t kvso = (uint32_t)(r2 * AQS + c2) * 4;

    auto issueKV = [&](int kt, int buf) {
        const uint32_t kb = smb + (uint32_t)(AT_Q + 2 * buf * AT_KV) * 4 + kvso;
        const uint32_t vb = kb + (uint32_t)AT_KV * 4;
        const float* kp = Kg0 + (size_t)(kt * 64 + r2) * Dh + c2;
        const float* vp = Vg0 + (size_t)(kt * 64 + r2) * Dh + c2;
#pragma unroll
        for (int i = 0; i < 4; i++) {
            cpa16(kb + i * 16, kp + i * 4);
            cpa16(vb + i * 16, vp + i * 4);
        }
        cpa_commit();
    };

    // Q tile [128x64] via cp.async (group 0, shared with KV0)
    {
        const float* Qg = g_q + ((size_t)bh * Sq + qbase) * Dh;
        const int r = tid >> 1, c0 = (tid & 1) << 5;
        const uint32_t qa = smb + (uint32_t)(r * AQS + c0) * 4;
        const float* qp = Qg + (size_t)r * Dh + c0;
#pragma unroll
        for (int i = 0; i < 8; i++) cpa16(qa + i * 16, qp + i * 4);
    }
    issueKV(0, 0);   // commits Q+KV0 as one group

    float m0 = -1e30f, m1 = -1e30f, l0 = 0.f, l1 = 0.f;
    float o[8][4];
#pragma unroll
    for (int nt = 0; nt < 8; nt++)
#pragma unroll
        for (int d = 0; d < 4; d++) o[nt][d] = 0.f;

    const int ktmax = 2 * qt + 1;
    for (int kt = 0; kt <= ktmax; kt++) {
        if (kt < ktmax) { issueKV(kt + 1, (kt + 1) & 1); cpa_wait<1>(); }
        else            { cpa_wait<0>(); }
        __syncthreads();

        const int kvbase = kt * 64;
        if (kvbase <= qbase + wr0 + 15) {           // warp not fully masked
            const uint32_t* Ks = sma + AT_Q + 2 * (kt & 1) * AT_KV;
            const uint32_t* Vs = Ks + AT_KV;

            // S = Q K^T
            float sc[8][4];
#pragma unroll
            for (int nt = 0; nt < 8; nt++)
#pragma unroll
                for (int d = 0; d < 4; d++) sc[nt][d] = 0.f;

            const uint32_t* qb = Qs + (wr0 + lq) * AQS + lr;
            const uint32_t* kb = Ks + lq * AQS + lr;
#pragma unroll
            for (int kk = 0; kk < 64; kk += 8) {
                uint32_t af[4];
                af[0] = qb[kk];
                af[1] = qb[8 * AQS + kk];
                af[2] = qb[kk + 4];
                af[3] = qb[8 * AQS + kk + 4];
#pragma unroll
                for (int nt = 0; nt < 8; nt++) {
                    uint32_t bf[2];
                    bf[0] = kb[nt * 8 * AQS + kk];
                    bf[1] = kb[nt * 8 * AQS + kk + 4];
                    mma8(sc[nt], af, bf);
                }
            }

            // causal mask
            const int row0 = qbase + wr0 + lq, row1 = row0 + 8;
            if (kvbase + 63 > row0) {
#pragma unroll
                for (int nt = 0; nt < 8; nt++) {
                    const int cg = kvbase + nt * 8 + (lr << 1);
                    if (cg > row0)     sc[nt][0] = -1e30f;
                    if (cg + 1 > row0) sc[nt][1] = -1e30f;
                    if (cg > row1)     sc[nt][2] = -1e30f;
                    if (cg + 1 > row1) sc[nt][3] = -1e30f;
                }
            }

            // online softmax (rows row0, row1)
            float mx0 = -1e30f, mx1 = -1e30f;
#pragma unroll
            for (int nt = 0; nt < 8; nt++) {
                mx0 = fmaxf(mx0, fmaxf(sc[nt][0], sc[nt][1]));
                mx1 = fmaxf(mx1, fmaxf(sc[nt][2], sc[nt][3]));
            }
            mx0 = fmaxf(mx0, __shfl_xor_sync(0xffffffffu, mx0, 1));
            mx0 = fmaxf(mx0, __shfl_xor_sync(0xffffffffu, mx0, 2));
            mx1 = fmaxf(mx1, __shfl_xor_sync(0xffffffffu, mx1, 1));
            mx1 = fmaxf(mx1, __shfl_xor_sync(0xffffffffu, mx1, 2));
            const float mn0 = fmaxf(m0, mx0), mn1 = fmaxf(m1, mx1);
            const float cr0 = __expf(m0 - mn0), cr1 = __expf(m1 - mn1);
            float s0 = 0.f, s1 = 0.f;
#pragma unroll
            for (int nt = 0; nt < 8; nt++) {
                sc[nt][0] = __expf(sc[nt][0] - mn0); s0 += sc[nt][0];
                sc[nt][1] = __expf(sc[nt][1] - mn0); s0 += sc[nt][1];
                sc[nt][2] = __expf(sc[nt][2] - mn1); s1 += sc[nt][2];
                sc[nt][3] = __expf(sc[nt][3] - mn1); s1 += sc[nt][3];
            }
            s0 += __shfl_xor_sync(0xffffffffu, s0, 1);
            s0 += __shfl_xor_sync(0xffffffffu, s0, 2);
            s1 += __shfl_xor_sync(0xffffffffu, s1, 1);
            s1 += __shfl_xor_sync(0xffffffffu, s1, 2);
            l0 = l0 * cr0 + s0; m0 = mn0;
            l1 = l1 * cr1 + s1; m1 = mn1;
#pragma unroll
            for (int nt = 0; nt < 8; nt++) {
                o[nt][0] *= cr0; o[nt][1] *= cr0;
                o[nt][2] *= cr1; o[nt][3] *= cr1;
            }

            // O += P V with P transposed c-frag -> a-frag via quad shuffles (no smem)
            const uint32_t* vb = Vs + lr * AQS + lq;
            const int srcA = (lane & ~3) | (lr >> 1);
            const int srcB = srcA + 2;
            const bool odd = lr & 1;
#pragma unroll
            for (int nt = 0; nt < 8; nt++) {
                uint32_t u0 = f2tf32(sc[nt][0]), u1 = f2tf32(sc[nt][1]);
                uint32_t u2 = f2tf32(sc[nt][2]), u3 = f2tf32(sc[nt][3]);
                uint32_t g0a = __shfl_sync(0xffffffffu, u0, srcA);
                uint32_t g1a = __shfl_sync(0xffffffffu, u1, srcA);
                uint32_t g2a = __shfl_sync(0xffffffffu, u2, srcA);
                uint32_t g3a = __shfl_sync(0xffffffffu, u3, srcA);
                uint32_t g0b = __shfl_sync(0xffffffffu, u0, srcB);
                uint32_t g1b = __shfl_sync(0xffffffffu, u1, srcB);
                uint32_t g2b = __shfl_sync(0xffffffffu, u2, srcB);
                uint32_t g3b = __shfl_sync(0xffffffffu, u3, srcB);
                uint32_t af[4];
                af[0] = odd ? g1a : g0a;
                af[1] = odd ? g3a : g2a;
                af[2] = odd ? g1b : g0b;
                af[3] = odd ? g3b : g2b;
                const int kk = nt * 8;
#pragma unroll
                for (int nt2 = 0; nt2 < 8; nt2++) {
                    uint32_t bf[2];
                    bf[0] = vb[kk * AQS + nt2 * 8];
                    bf[1] = vb[(kk + 4) * AQS + nt2 * 8];
                    mma8(o[nt2], af, bf);
                }
            }
        }
        __syncthreads();
    }

    // write O (tf32-rounded for outproj)
    const int b_ = bh >> 4, h_ = bh & 15;
    const int r0g = qbase + wr0 + lq, r1g = r0g + 8;
    const float i0 = 1.0f / l0, i1 = 1.0f / l1;
#pragma unroll
    for (int nt = 0; nt < 8; nt++) {
        const int col = h_ * Dh + nt * 8 + (lr << 1);
        float2 v0 = {tf32r(o[nt][0] * i0), tf32r(o[nt][1] * i0)};
        float2 v1 = {tf32r(o[nt][2] * i1), tf32r(o[nt][3] * i1)};
        *(float2*)(g_attn + ((size_t)b_ * Sq + r0g) * Dm + col) = v0;
        *(float2*)(g_attn + ((size_t)b_ * Sq + r1g) * Dm + col) = v1;
    }
}

// ===================== launch =====================
extern "C" void kernel_launch(void* const* d_in, const int* in_sizes, int n_in,
                              void* d_out, int out_size) {
    const float* x    = (const float*)d_in[0];
    const float* w    = (const float*)d_in[1];
    const float* Wq   = (const float*)d_in[2];
    const float* bq   = (const float*)d_in[3];
    const float* Wk   = (const float*)d_in[4];
    const float* bk   = (const float*)d_in[5];
    const float* Wv   = (const float*)d_in[6];
    const float* bv   = (const float*)d_in[7];
    const float* Wout = (const float*)d_in[8];
    const float* bout = (const float*)d_in[9];
    float* out = (float*)d_out;

    prep_kernel<<<2048, 512>>>(w, x, Wq, Wk, Wv, bq, bk, bv, Wout, bout);

    cudaFuncSetAttribute(proj_mma, cudaFuncAttributeMaxDynamicSharedMemorySize, GEMM_DYN);
    proj_mma<<<dim3(3 * Dm / BN, Mrows / BM), 256, GEMM_DYN>>>();

    cudaFuncSetAttribute(attn_mma, cudaFuncAttributeMaxDynamicSharedMemorySize, AT_DYN);
    attn_mma<<<dim3(Sq / 128, Bb * Hh), 256, AT_DYN>>>();

    cudaFuncSetAttribute(outproj_mma, cudaFuncAttributeMaxDynamicSharedMemorySize, GEMM_DYN);
    outproj_mma<<<dim3(Dm / BN, Mrows / BM), 256, GEMM_DYN>>>(out);
}

// round 9
// speedup vs baseline: 6.5889x; 2.0367x over previous
#include <cuda_runtime.h>
#include <cuda_fp16.h>
#include <cstdint>

// Problem constants
constexpr int Bb = 2, Sq = 2048, Dm = 1024, Hh = 16, Dh = 64;
constexpr int Mrows = Bb * Sq; // 4096

// Scratch (no cudaMalloc allowed)
__device__ __half g_q[Bb * Hh * Sq * Dh];     // [B,H,S,DH] fp16, Q pre-scaled by 1/8
__device__ __half g_k[Bb * Hh * Sq * Dh];     // [B,H,S,DH] fp16
__device__ __half g_v[Bb * Hh * Dh * Sq];     // [B,H,DH,S] fp16 (TRANSPOSED)
__device__ __half g_attn[Bb * Sq * Dm];       // fp16
__device__ __half g_Weff[Dm * Dm];            // fp16
__device__ float  g_beff[Dm];                 // fp32
__device__ __half g_xt[Bb * Sq * Dm];         // fp16 x
__device__ __half g_wcat[3 * Dm * Dm];        // fp16 Wq|Wk|Wv
__device__ float  g_bcat[3 * Dm];             // bq|bk|bv fp32

// ===================== helpers =====================
__device__ __forceinline__ uint32_t h2pack(float lo, float hi) {
    __half2 h = __floats2half2_rn(lo, hi);
    return *(uint32_t*)&h;
}
__device__ __forceinline__ uint32_t smem_u32(const void* p) {
    uint32_t a;
    asm("{ .reg .u64 t; cvta.to.shared.u64 t, %1; cvt.u32.u64 %0, t; }" : "=r"(a) : "l"(p));
    return a;
}
__device__ __forceinline__ void cpa16(uint32_t d, const void* s) {
    asm volatile("cp.async.cg.shared.global [%0], [%1], 16;" :: "r"(d), "l"(s));
}
__device__ __forceinline__ void cpa_commit() {
    asm volatile("cp.async.commit_group;" ::: "memory");
}
template <int N>
__device__ __forceinline__ void cpa_wait() {
    asm volatile("cp.async.wait_group %0;" :: "n"(N) : "memory");
}
// D(16x8,f32) += A(16x16 f16) * B(16x8 f16)
__device__ __forceinline__ void mma16(float* c, const uint32_t* a, const uint32_t* b) {
    asm volatile(
        "mma.sync.aligned.m16n8k16.row.col.f32.f16.f16.f32 "
        "{%0,%1,%2,%3}, {%4,%5,%6,%7}, {%8,%9}, {%0,%1,%2,%3};"
        : "+f"(c[0]), "+f"(c[1]), "+f"(c[2]), "+f"(c[3])
        : "r"(a[0]), "r"(a[1]), "r"(a[2]), "r"(a[3]), "r"(b[0]), "r"(b[1]));
}

// ===================== prep: fp16 conversions + combines =====================
__global__ void prep_kernel(const float* __restrict__ w,  const float* __restrict__ x,
                            const float* __restrict__ Wq, const float* __restrict__ Wk,
                            const float* __restrict__ Wv,
                            const float* __restrict__ bq, const float* __restrict__ bk,
                            const float* __restrict__ bv,
                            const float* __restrict__ Wout, const float* __restrict__ bout) {
    const float w0 = w[0], w1 = w[1], w2 = w[2], w3 = w[3];
    const float4* x4  = (const float4*)x;
    const float4* wq4 = (const float4*)Wq;
    const float4* wk4 = (const float4*)Wk;
    const float4* wv4 = (const float4*)Wv;
    const float4* wo4 = (const float4*)Wout;
    uint2* xt = (uint2*)g_xt;
    uint2* wc = (uint2*)g_wcat;
    uint2* we = (uint2*)g_Weff;
    constexpr int NX = Mrows * Dm / 4;       // 1048576
    constexpr int NW = Dm * Dm / 4;          // 262144
    for (int i = blockIdx.x * blockDim.x + threadIdx.x; i < NX; i += gridDim.x * blockDim.x) {
        float4 v = x4[i];
        xt[i] = make_uint2(h2pack(v.x, v.y), h2pack(v.z, v.w));
        if (i < NW) {
            float4 a = wq4[i];
            wc[i] = make_uint2(h2pack(a.x, a.y), h2pack(a.z, a.w));
            a = wk4[i];
            wc[i + NW] = make_uint2(h2pack(a.x, a.y), h2pack(a.z, a.w));
            a = wv4[i];
            wc[i + 2 * NW] = make_uint2(h2pack(a.x, a.y), h2pack(a.z, a.w));
            float4 p = wo4[i], q = wo4[i + NW], r = wo4[i + 2 * NW], s = wo4[i + 3 * NW];
            float4 e;
            e.x = w0 * p.x + w1 * q.x + w2 * r.x + w3 * s.x;
            e.y = w0 * p.y + w1 * q.y + w2 * r.y + w3 * s.y;
            e.z = w0 * p.z + w1 * q.z + w2 * r.z + w3 * s.z;
            e.w = w0 * p.w + w1 * q.w + w2 * r.w + w3 * s.w;
            we[i] = make_uint2(h2pack(e.x, e.y), h2pack(e.z, e.w));
        }
        if (i < 3 * Dm) {
            const int z = i >> 10, j = i & 1023;
            g_bcat[i] = (z == 0) ? bq[j] : (z == 1) ? bk[j] : bv[j];
        }
        if (i < Dm) {
            g_beff[i] = w0 * bout[i] + w1 * bout[i + Dm]
                      + w2 * bout[i + 2 * Dm] + w3 * bout[i + 3 * Dm];
        }
    }
}

// ======== fp16 NT GEMM: CTA 256x128, 256 thr, warp tile 64x64, 4-stage ring ========
// Tiles stored as 32-bit words (half2). BK = 64 halves = 32 words per row per stage.
constexpr int BM = 256, BN = 128, BKH = 64, BKW = 32;
constexpr int SKW = BKW + 4;                    // padded stride (words); 144B
constexpr int TILEA = BM * SKW;                 // 9216 words
constexpr int TILEB = BN * SKW;                 // 4608 words
constexpr int STAGEU = TILEA + TILEB;           // 13824 words
constexpr int NST = 4;
constexpr int GEMM_DYN = NST * STAGEU * 4;      // 221184 B
constexpr int NSTAGE = Dm / BKH;                // 16

template <int MODE>  // 0 = QKV epilogue (fp16 out, V transposed), 1 = plain fp32
__device__ __forceinline__ void gemm_core(
    const __half* __restrict__ A, const __half* __restrict__ W,
    const float* __restrict__ bias, float scale, void* __restrict__ outp,
    int rowBase, int colBase, int zsel)
{
    extern __shared__ uint32_t smg[];
    const uint32_t smb = smem_u32(smg);
    const int tid = threadIdx.x, wid = tid >> 5, lane = tid & 31;
    const int lq = lane >> 2, lr = lane & 3;
    const int warpM = wid & 3, warpN = wid >> 2;       // 4 x 2 warps, warp tile 64x64

    // Loaders: 2 thr/row, 64B (4x16B) each = 128B/row. A rows 0..127 & 128..255; B 128 rows.
    const int rowL = tid >> 1;
    const int khh = (tid & 1) << 5;                    // half offset 0/32
    const __half* Ap0 = A + (size_t)(rowBase + rowL) * Dm + khh;
    const __half* Ap1 = Ap0 + (size_t)128 * Dm;
    const __half* Bp  = W + (size_t)(colBase + rowL) * Dm + khh;
    const uint32_t saA0 = smb + (uint32_t)(rowL * SKW + (khh >> 1)) * 4;
    const uint32_t saA1 = saA0 + (uint32_t)(128 * SKW) * 4;
    const uint32_t saB  = smb + (uint32_t)(TILEA + rowL * SKW + (khh >> 1)) * 4;

    auto issue = [&](int s) {
        const uint32_t off = (uint32_t)((s % NST) * STAGEU) * 4;
        const __half* ga0 = Ap0 + s * BKH;
        const __half* ga1 = Ap1 + s * BKH;
        const __half* gb  = Bp + s * BKH;
#pragma unroll
        for (int i = 0; i < 4; i++) {
            cpa16(saA0 + off + i * 16, ga0 + i * 8);
            cpa16(saA1 + off + i * 16, ga1 + i * 8);
            cpa16(saB  + off + i * 16, gb  + i * 8);
        }
        cpa_commit();
    };

    float c[4][8][4];
#pragma unroll
    for (int a = 0; a < 4; a++)
#pragma unroll
        for (int b = 0; b < 8; b++)
#pragma unroll
            for (int d = 0; d < 4; d++) c[a][b][d] = 0.f;

    issue(0); issue(1); issue(2);

    for (int s = 0; s < NSTAGE; s++) {
        if (s + 2 < NSTAGE) cpa_wait<2>(); else cpa_wait<0>();
        __syncthreads();
        if (s + 3 < NSTAGE) issue(s + 3);

        const uint32_t* As = smg + (s % NST) * STAGEU;
        const uint32_t* Bs = As + TILEA;
        const uint32_t* abase = As + (warpM * 64 + lq) * SKW + lr;
        const uint32_t* bbase = Bs + (warpN * 64 + lq) * SKW + lr;
#pragma unroll
        for (int kk = 0; kk < BKW; kk += 8) {          // 4 k16 steps
            uint32_t af[4][4];
#pragma unroll
            for (int mt = 0; mt < 4; mt++) {
                const uint32_t* p = abase + mt * 16 * SKW + kk;
                af[mt][0] = p[0];
                af[mt][1] = p[8 * SKW];
                af[mt][2] = p[4];
                af[mt][3] = p[8 * SKW + 4];
            }
            uint32_t bf[8][2];
#pragma unroll
            for (int nt = 0; nt < 8; nt++) {
                const uint32_t* p = bbase + nt * 8 * SKW + kk;
                bf[nt][0] = p[0];
                bf[nt][1] = p[4];
            }
#pragma unroll
            for (int mt = 0; mt < 4; mt++)
#pragma unroll
                for (int nt = 0; nt < 8; nt++)
                    mma16(c[mt][nt], af[mt], bf[nt]);
        }
    }

    // Epilogue. C frag (mt,nt): rows lq (+8), cols lr*2 (+1)
#pragma unroll
    for (int mt = 0; mt < 4; mt++) {
        const int r0 = rowBase + warpM * 64 + mt * 16 + lq;
#pragma unroll
        for (int nt = 0; nt < 8; nt++) {
            const int n = colBase + warpN * 64 + nt * 8 + (lr << 1);
            float bx = bias[n], by = bias[n + 1];
#pragma unroll
            for (int half_ = 0; half_ < 2; half_++) {
                const int m = r0 + half_ * 8;
                float vx = (c[mt][nt][half_ * 2 + 0] + bx) * scale;
                float vy = (c[mt][nt][half_ * 2 + 1] + by) * scale;
                if (MODE == 0) {
                    const int b_ = m >> 11, s_ = m & 2047, h_ = n >> 6, d0 = n & 63;
                    __half* out = (__half*)outp;
                    if (zsel == 2) {   // V: transposed [B,H,DH,S]
                        const size_t base = ((size_t)(b_ * Hh + h_) * Dh + d0) * Sq + s_;
                        out[base] = __float2half_rn(vx);
                        out[base + Sq] = __float2half_rn(vy);
                    } else {           // Q/K: [B,H,S,DH]
                        *(uint32_t*)(out + ((size_t)(b_ * Hh + h_) * Sq + s_) * Dh + d0)
                            = h2pack(vx, vy);
                    }
                } else {
                    *(float2*)((float*)outp + (size_t)m * Dm + n) = make_float2(vx, vy);
                }
            }
        }
    }
}

// Fused QKV projection: N = 3072 (Wq|Wk|Wv)
__global__ __launch_bounds__(256, 1) void proj_mma()
{
    const int nGlob = blockIdx.x * BN;          // 0..2944
    const int z = nGlob >> 10;                  // 0,1,2
    const int colLocal = nGlob & 1023;
    const __half* W   = g_wcat + (size_t)z * Dm * Dm;
    const float* bias = g_bcat + z * Dm;
    __half* out       = (z == 0) ? g_q : (z == 1) ? g_k : g_v;
    const float scale = (z == 0) ? 0.125f : 1.0f;
    gemm_core<0>(g_xt, W, bias, scale, out, blockIdx.y * BM, colLocal, z);
}

__global__ __launch_bounds__(256, 1) void outproj_mma(float* __restrict__ Out)
{
    gemm_core<1>(g_attn, g_Weff, g_beff, 1.0f, Out, blockIdx.y * BM, blockIdx.x * BN, 0);
}

// ===================== flash attention, fp16 (no P smem, no shuffles) =====================
// BQ=128 (8 warps x m16), BKV=64, DH=64. Q + double-buffered K/V in smem (half2 words).
constexpr int AQW = 36;                           // stride (words) for all attn tiles
constexpr int AT_Q = 128 * AQW;                   // Q tile words
constexpr int AT_KV = 64 * AQW;                   // one K or V tile (64 rows x 32 words)
constexpr int AT_DYN = (AT_Q + 4 * AT_KV) * 4;    // 55296 B

__global__ __launch_bounds__(256, 2) void attn_mma()
{
    extern __shared__ uint32_t sma[];
    uint32_t* Qs = sma;
    const uint32_t smb = smem_u32(sma);

    const int tid = threadIdx.x, wid = tid >> 5, lane = tid & 31;
    const int lq = lane >> 2, lr = lane & 3;
    const int qt = gridDim.x - 1 - blockIdx.x;    // big tiles first
    const int bh = blockIdx.y;
    const int qbase = qt * 128;
    const int wr0 = wid * 16;                     // warp's local q-row base

    const __half* Kg0 = g_k + (size_t)bh * Sq * Dh;           // [s][dh]
    const __half* Vg0 = g_v + (size_t)bh * Dh * Sq;           // [dh][s]

    // K/V loader mapping: 4 threads per row, 32B (2x16B) each; 64 rows
    const int r4 = tid >> 2, c4h = (tid & 3) << 4;            // half offset 0/16/32/48
    const uint32_t kvso = (uint32_t)(r4 * AQW + (c4h >> 1)) * 4;

    auto issueKV = [&](int kt, int buf) {
        const uint32_t kb = smb + (uint32_t)(AT_Q + 2 * buf * AT_KV) * 4 + kvso;
        const uint32_t vb = kb + (uint32_t)AT_KV * 4;
        const __half* kp = Kg0 + (size_t)(kt * 64 + r4) * Dh + c4h;
        const __half* vp = Vg0 + (size_t)r4 * Sq + kt * 64 + c4h;
#pragma unroll
        for (int i = 0; i < 2; i++) {
            cpa16(kb + i * 16, kp + i * 8);
            cpa16(vb + i * 16, vp + i * 8);
        }
        cpa_commit();
    };

    // Q tile [128 x 64 halves]: 2 thr/row, 64B each
    {
        const __half* Qg = g_q + ((size_t)bh * Sq + qbase) * Dh;
        const int r = tid >> 1, c0h = (tid & 1) << 5;
        const uint32_t qa = smb + (uint32_t)(r * AQW + (c0h >> 1)) * 4;
        const __half* qp = Qg + (size_t)r * Dh + c0h;
#pragma unroll
        for (int i = 0; i < 4; i++) cpa16(qa + i * 16, qp + i * 8);
    }
    issueKV(0, 0);   // commits Q+KV0 as one group

    float m0 = -1e30f, m1 = -1e30f, l0 = 0.f, l1 = 0.f;
    float o[8][4];
#pragma unroll
    for (int nt = 0; nt < 8; nt++)
#pragma unroll
        for (int d = 0; d < 4; d++) o[nt][d] = 0.f;

    const int ktmax = 2 * qt + 1;
    for (int kt = 0; kt <= ktmax; kt++) {
        if (kt < ktmax) { issueKV(kt + 1, (kt + 1) & 1); cpa_wait<1>(); }
        else            { cpa_wait<0>(); }
        __syncthreads();

        const int kvbase = kt * 64;
        if (kvbase <= qbase + wr0 + 15) {           // warp not fully masked
            const uint32_t* Ks = sma + AT_Q + 2 * (kt & 1) * AT_KV;
            const uint32_t* Vs = Ks + AT_KV;

            // S = Q K^T  (4 k16 steps over DH=64)
            float sc[8][4];
#pragma unroll
            for (int nt = 0; nt < 8; nt++)
#pragma unroll
                for (int d = 0; d < 4; d++) sc[nt][d] = 0.f;

            const uint32_t* qb = Qs + (wr0 + lq) * AQW + lr;
            const uint32_t* kb = Ks + lq * AQW + lr;
#pragma unroll
            for (int kk = 0; kk < 32; kk += 8) {
                uint32_t af[4];
                af[0] = qb[kk];
                af[1] = qb[8 * AQW + kk];
                af[2] = qb[kk + 4];
                af[3] = qb[8 * AQW + kk + 4];
#pragma unroll
                for (int nt = 0; nt < 8; nt++) {
                    uint32_t bf[2];
                    bf[0] = kb[nt * 8 * AQW + kk];
                    bf[1] = kb[nt * 8 * AQW + kk + 4];
                    mma16(sc[nt], af, bf);
                }
            }

            // causal mask
            const int row0 = qbase + wr0 + lq, row1 = row0 + 8;
            if (kvbase + 63 > row0) {
#pragma unroll
                for (int nt = 0; nt < 8; nt++) {
                    const int cg = kvbase + nt * 8 + (lr << 1);
                    if (cg > row0)     sc[nt][0] = -1e30f;
                    if (cg + 1 > row0) sc[nt][1] = -1e30f;
                    if (cg > row1)     sc[nt][2] = -1e30f;
                    if (cg + 1 > row1) sc[nt][3] = -1e30f;
                }
            }

            // online softmax (rows row0, row1)
            float mx0 = -1e30f, mx1 = -1e30f;
#pragma unroll
            for (int nt = 0; nt < 8; nt++) {
                mx0 = fmaxf(mx0, fmaxf(sc[nt][0], sc[nt][1]));
                mx1 = fmaxf(mx1, fmaxf(sc[nt][2], sc[nt][3]));
            }
            mx0 = fmaxf(mx0, __shfl_xor_sync(0xffffffffu, mx0, 1));
            mx0 = fmaxf(mx0, __shfl_xor_sync(0xffffffffu, mx0, 2));
            mx1 = fmaxf(mx1, __shfl_xor_sync(0xffffffffu, mx1, 1));
            mx1 = fmaxf(mx1, __shfl_xor_sync(0xffffffffu, mx1, 2));
            const float mn0 = fmaxf(m0, mx0), mn1 = fmaxf(m1, mx1);
            const float cr0 = __expf(m0 - mn0), cr1 = __expf(m1 - mn1);
            float s0 = 0.f, s1 = 0.f;
#pragma unroll
            for (int nt = 0; nt < 8; nt++) {
                sc[nt][0] = __expf(sc[nt][0] - mn0); s0 += sc[nt][0];
                sc[nt][1] = __expf(sc[nt][1] - mn0); s0 += sc[nt][1];
                sc[nt][2] = __expf(sc[nt][2] - mn1); s1 += sc[nt][2];
                sc[nt][3] = __expf(sc[nt][3] - mn1); s1 += sc[nt][3];
            }
            s0 += __shfl_xor_sync(0xffffffffu, s0, 1);
            s0 += __shfl_xor_sync(0xffffffffu, s0, 2);
            s1 += __shfl_xor_sync(0xffffffffu, s1, 1);
            s1 += __shfl_xor_sync(0xffffffffu, s1, 2);
            l0 = l0 * cr0 + s0; m0 = mn0;
            l1 = l1 * cr1 + s1; m1 = mn1;
#pragma unroll
            for (int nt = 0; nt < 8; nt++) {
                o[nt][0] *= cr0; o[nt][1] *= cr0;
                o[nt][2] *= cr1; o[nt][3] *= cr1;
            }

            // O += P V : fp16 c-frag IS the a-frag layout — just pack pairs. 4 k16 steps.
#pragma unroll
            for (int st = 0; st < 4; st++) {
                uint32_t af[4];
                af[0] = h2pack(sc[2 * st][0],     sc[2 * st][1]);
                af[1] = h2pack(sc[2 * st][2],     sc[2 * st][3]);
                af[2] = h2pack(sc[2 * st + 1][0], sc[2 * st + 1][1]);
                af[3] = h2pack(sc[2 * st + 1][2], sc[2 * st + 1][3]);
#pragma unroll
                for (int nt2 = 0; nt2 < 8; nt2++) {
                    const uint32_t* p = Vs + (nt2 * 8 + lq) * AQW + st * 8 + lr;
                    uint32_t bf[2];
                    bf[0] = p[0];
                    bf[1] = p[4];
                    mma16(o[nt2], af, bf);
                }
            }
        }
        __syncthreads();
    }

    // write O (fp16) to g_attn [B,S,D]
    const int b_ = bh >> 4, h_ = bh & 15;
    const int r0g = qbase + wr0 + lq, r1g = r0g + 8;
    const float i0 = 1.0f / l0, i1 = 1.0f / l1;
#pragma unroll
    for (int nt = 0; nt < 8; nt++) {
        const int col = h_ * Dh + nt * 8 + (lr << 1);
        *(uint32_t*)(g_attn + ((size_t)b_ * Sq + r0g) * Dm + col)
            = h2pack(o[nt][0] * i0, o[nt][1] * i0);
        *(uint32_t*)(g_attn + ((size_t)b_ * Sq + r1g) * Dm + col)
            = h2pack(o[nt][2] * i1, o[nt][3] * i1);
    }
}

// ===================== launch =====================
extern "C" void kernel_launch(void* const* d_in, const int* in_sizes, int n_in,
                              void* d_out, int out_size) {
    const float* x    = (const float*)d_in[0];
    const float* w    = (const float*)d_in[1];
    const float* Wq   = (const float*)d_in[2];
    const float* bq   = (const float*)d_in[3];
    const float* Wk   = (const float*)d_in[4];
    const float* bk   = (const float*)d_in[5];
    const float* Wv   = (const float*)d_in[6];
    const float* bv   = (const float*)d_in[7];
    const float* Wout = (const float*)d_in[8];
    const float* bout = (const float*)d_in[9];
    float* out = (float*)d_out;

    prep_kernel<<<2048, 512>>>(w, x, Wq, Wk, Wv, bq, bk, bv, Wout, bout);

    cudaFuncSetAttribute(proj_mma, cudaFuncAttributeMaxDynamicSharedMemorySize, GEMM_DYN);
    proj_mma<<<dim3(3 * Dm / BN, Mrows / BM), 256, GEMM_DYN>>>();

    cudaFuncSetAttribute(attn_mma, cudaFuncAttributeMaxDynamicSharedMemorySize, AT_DYN);
    attn_mma<<<dim3(Sq / 128, Bb * Hh), 256, AT_DYN>>>();

    cudaFuncSetAttribute(outproj_mma, cudaFuncAttributeMaxDynamicSharedMemorySize, GEMM_DYN);
    outproj_mma<<<dim3(Dm / BN, Mrows / BM), 256, GEMM_DYN>>>(out);
}

// round 10
// speedup vs baseline: 6.6374x; 1.0074x over previous
#include <cuda_runtime.h>
#include <cuda_fp16.h>
#include <cstdint>

// Problem constants
constexpr int Bb = 2, Sq = 2048, Dm = 1024, Hh = 16, Dh = 64;
constexpr int Mrows = Bb * Sq; // 4096

// Scratch (no cudaMalloc allowed)
__device__ __half g_q[Bb * Hh * Sq * Dh];     // [B,H,S,DH] fp16, Q pre-scaled by 1/8
__device__ __half g_k[Bb * Hh * Sq * Dh];     // [B,H,S,DH] fp16
__device__ __half g_v[Bb * Hh * Dh * Sq];     // [B,H,DH,S] fp16 (TRANSPOSED)
__device__ __half g_attn[Bb * Sq * Dm];       // fp16
__device__ __half g_Weff[Dm * Dm];            // fp16
__device__ float  g_beff[Dm];                 // fp32
__device__ __half g_xt[Bb * Sq * Dm];         // fp16 x
__device__ __half g_wcat[3 * Dm * Dm];        // fp16 Wq|Wk|Wv
__device__ float  g_bcat[3 * Dm];             // bq|bk|bv fp32

// ===================== helpers =====================
__device__ __forceinline__ uint32_t h2pack(float lo, float hi) {
    __half2 h = __floats2half2_rn(lo, hi);
    return *(uint32_t*)&h;
}
__device__ __forceinline__ uint32_t smem_u32(const void* p) {
    uint32_t a;
    asm("{ .reg .u64 t; cvta.to.shared.u64 t, %1; cvt.u32.u64 %0, t; }" : "=r"(a) : "l"(p));
    return a;
}
__device__ __forceinline__ void cpa16(uint32_t d, const void* s) {
    asm volatile("cp.async.cg.shared.global [%0], [%1], 16;" :: "r"(d), "l"(s));
}
__device__ __forceinline__ void cpa_commit() {
    asm volatile("cp.async.commit_group;" ::: "memory");
}
template <int N>
__device__ __forceinline__ void cpa_wait() {
    asm volatile("cp.async.wait_group %0;" :: "n"(N) : "memory");
}
// D(16x8,f32) += A(16x16 f16) * B(16x8 f16)
__device__ __forceinline__ void mma16(float* c, const uint32_t* a, const uint32_t* b) {
    asm volatile(
        "mma.sync.aligned.m16n8k16.row.col.f32.f16.f16.f32 "
        "{%0,%1,%2,%3}, {%4,%5,%6,%7}, {%8,%9}, {%0,%1,%2,%3};"
        : "+f"(c[0]), "+f"(c[1]), "+f"(c[2]), "+f"(c[3])
        : "r"(a[0]), "r"(a[1]), "r"(a[2]), "r"(a[3]), "r"(b[0]), "r"(b[1]));
}

// ===================== prep: fp16 conversions + combines =====================
__global__ void prep_kernel(const float* __restrict__ w,  const float* __restrict__ x,
                            const float* __restrict__ Wq, const float* __restrict__ Wk,
                            const float* __restrict__ Wv,
                            const float* __restrict__ bq, const float* __restrict__ bk,
                            const float* __restrict__ bv,
                            const float* __restrict__ Wout, const float* __restrict__ bout) {
    const float w0 = w[0], w1 = w[1], w2 = w[2], w3 = w[3];
    const float4* x4  = (const float4*)x;
    const float4* wq4 = (const float4*)Wq;
    const float4* wk4 = (const float4*)Wk;
    const float4* wv4 = (const float4*)Wv;
    const float4* wo4 = (const float4*)Wout;
    uint2* xt = (uint2*)g_xt;
    uint2* wc = (uint2*)g_wcat;
    uint2* we = (uint2*)g_Weff;
    constexpr int NX = Mrows * Dm / 4;       // 1048576
    constexpr int NW = Dm * Dm / 4;          // 262144
    for (int i = blockIdx.x * blockDim.x + threadIdx.x; i < NX; i += gridDim.x * blockDim.x) {
        float4 v = x4[i];
        xt[i] = make_uint2(h2pack(v.x, v.y), h2pack(v.z, v.w));
        if (i < NW) {
            float4 a = wq4[i];
            wc[i] = make_uint2(h2pack(a.x, a.y), h2pack(a.z, a.w));
            a = wk4[i];
            wc[i + NW] = make_uint2(h2pack(a.x, a.y), h2pack(a.z, a.w));
            a = wv4[i];
            wc[i + 2 * NW] = make_uint2(h2pack(a.x, a.y), h2pack(a.z, a.w));
            float4 p = wo4[i], q = wo4[i + NW], r = wo4[i + 2 * NW], s = wo4[i + 3 * NW];
            float4 e;
            e.x = w0 * p.x + w1 * q.x + w2 * r.x + w3 * s.x;
            e.y = w0 * p.y + w1 * q.y + w2 * r.y + w3 * s.y;
            e.z = w0 * p.z + w1 * q.z + w2 * r.z + w3 * s.z;
            e.w = w0 * p.w + w1 * q.w + w2 * r.w + w3 * s.w;
            we[i] = make_uint2(h2pack(e.x, e.y), h2pack(e.z, e.w));
        }
        if (i < 3 * Dm) {
            const int z = i >> 10, j = i & 1023;
            g_bcat[i] = (z == 0) ? bq[j] : (z == 1) ? bk[j] : bv[j];
        }
        if (i < Dm) {
            g_beff[i] = w0 * bout[i] + w1 * bout[i + Dm]
                      + w2 * bout[i + 2 * Dm] + w3 * bout[i + 3 * Dm];
        }
    }
}

// ======== fp16 NT GEMM: CTA 256x128, 256 thr, warp tile 64x64, 4-stage ring ========
// Tiles stored as 32-bit words (half2). BK = 64 halves = 32 words per row per stage.
constexpr int BM = 256, BN = 128, BKH = 64, BKW = 32;
constexpr int SKW = BKW + 4;                    // padded stride (words); 144B
constexpr int TILEA = BM * SKW;                 // 9216 words
constexpr int TILEB = BN * SKW;                 // 4608 words
constexpr int STAGEU = TILEA + TILEB;           // 13824 words
constexpr int NST = 4;
constexpr int GEMM_DYN = NST * STAGEU * 4;      // 221184 B
constexpr int NSTAGE = Dm / BKH;                // 16

template <int MODE>  // 0 = QKV epilogue (fp16 out, V transposed), 1 = plain fp32
__device__ __forceinline__ void gemm_core(
    const __half* __restrict__ A, const __half* __restrict__ W,
    const float* __restrict__ bias, float scale, void* __restrict__ outp,
    int rowBase, int colBase, int zsel)
{
    extern __shared__ uint32_t smg[];
    const uint32_t smb = smem_u32(smg);
    const int tid = threadIdx.x, wid = tid >> 5, lane = tid & 31;
    const int lq = lane >> 2, lr = lane & 3;
    const int warpM = wid & 3, warpN = wid >> 2;       // 4 x 2 warps, warp tile 64x64

    // Loaders: 2 thr/row, 64B (4x16B) each = 128B/row. A rows 0..127 & 128..255; B 128 rows.
    const int rowL = tid >> 1;
    const int khh = (tid & 1) << 5;                    // half offset 0/32
    const __half* Ap0 = A + (size_t)(rowBase + rowL) * Dm + khh;
    const __half* Ap1 = Ap0 + (size_t)128 * Dm;
    const __half* Bp  = W + (size_t)(colBase + rowL) * Dm + khh;
    const uint32_t saA0 = smb + (uint32_t)(rowL * SKW + (khh >> 1)) * 4;
    const uint32_t saA1 = saA0 + (uint32_t)(128 * SKW) * 4;
    const uint32_t saB  = smb + (uint32_t)(TILEA + rowL * SKW + (khh >> 1)) * 4;

    auto issue = [&](int s) {
        const uint32_t off = (uint32_t)((s % NST) * STAGEU) * 4;
        const __half* ga0 = Ap0 + s * BKH;
        const __half* ga1 = Ap1 + s * BKH;
        const __half* gb  = Bp + s * BKH;
#pragma unroll
        for (int i = 0; i < 4; i++) {
            cpa16(saA0 + off + i * 16, ga0 + i * 8);
            cpa16(saA1 + off + i * 16, ga1 + i * 8);
            cpa16(saB  + off + i * 16, gb  + i * 8);
        }
        cpa_commit();
    };

    float c[4][8][4];
#pragma unroll
    for (int a = 0; a < 4; a++)
#pragma unroll
        for (int b = 0; b < 8; b++)
#pragma unroll
            for (int d = 0; d < 4; d++) c[a][b][d] = 0.f;

    issue(0); issue(1); issue(2);

    for (int s = 0; s < NSTAGE; s++) {
        if (s + 2 < NSTAGE) cpa_wait<2>(); else cpa_wait<0>();
        __syncthreads();
        if (s + 3 < NSTAGE) issue(s + 3);

        const uint32_t* As = smg + (s % NST) * STAGEU;
        const uint32_t* Bs = As + TILEA;
        const uint32_t* abase = As + (warpM * 64 + lq) * SKW + lr;
        const uint32_t* bbase = Bs + (warpN * 64 + lq) * SKW + lr;
#pragma unroll
        for (int kk = 0; kk < BKW; kk += 8) {          // 4 k16 steps
            uint32_t af[4][4];
#pragma unroll
            for (int mt = 0; mt < 4; mt++) {
                const uint32_t* p = abase + mt * 16 * SKW + kk;
                af[mt][0] = p[0];
                af[mt][1] = p[8 * SKW];
                af[mt][2] = p[4];
                af[mt][3] = p[8 * SKW + 4];
            }
            uint32_t bf[8][2];
#pragma unroll
            for (int nt = 0; nt < 8; nt++) {
                const uint32_t* p = bbase + nt * 8 * SKW + kk;
                bf[nt][0] = p[0];
                bf[nt][1] = p[4];
            }
#pragma unroll
            for (int mt = 0; mt < 4; mt++)
#pragma unroll
                for (int nt = 0; nt < 8; nt++)
                    mma16(c[mt][nt], af[mt], bf[nt]);
        }
    }

    // Epilogue. C frag (mt,nt): rows lq (+8), cols lr*2 (+1)
#pragma unroll
    for (int mt = 0; mt < 4; mt++) {
        const int r0 = rowBase + warpM * 64 + mt * 16 + lq;
#pragma unroll
        for (int nt = 0; nt < 8; nt++) {
            const int n = colBase + warpN * 64 + nt * 8 + (lr << 1);
            float bx = bias[n], by = bias[n + 1];
#pragma unroll
            for (int half_ = 0; half_ < 2; half_++) {
                const int m = r0 + half_ * 8;
                float vx = (c[mt][nt][half_ * 2 + 0] + bx) * scale;
                float vy = (c[mt][nt][half_ * 2 + 1] + by) * scale;
                if (MODE == 0) {
                    const int b_ = m >> 11, s_ = m & 2047, h_ = n >> 6, d0 = n & 63;
                    __half* out = (__half*)outp;
                    if (zsel == 2) {   // V: transposed [B,H,DH,S]
                        const size_t base = ((size_t)(b_ * Hh + h_) * Dh + d0) * Sq + s_;
                        out[base] = __float2half_rn(vx);
                        out[base + Sq] = __float2half_rn(vy);
                    } else {           // Q/K: [B,H,S,DH]
                        *(uint32_t*)(out + ((size_t)(b_ * Hh + h_) * Sq + s_) * Dh + d0)
                            = h2pack(vx, vy);
                    }
                } else {
                    *(float2*)((float*)outp + (size_t)m * Dm + n) = make_float2(vx, vy);
                }
            }
        }
    }
}

// Fused QKV projection: N = 3072 (Wq|Wk|Wv)
__global__ __launch_bounds__(256, 1) void proj_mma()
{
    const int nGlob = blockIdx.x * BN;          // 0..2944
    const int z = nGlob >> 10;                  // 0,1,2
    const int colLocal = nGlob & 1023;
    const __half* W   = g_wcat + (size_t)z * Dm * Dm;
    const float* bias = g_bcat + z * Dm;
    __half* out       = (z == 0) ? g_q : (z == 1) ? g_k : g_v;
    const float scale = (z == 0) ? 0.125f : 1.0f;
    gemm_core<0>(g_xt, W, bias, scale, out, blockIdx.y * BM, colLocal, z);
}

__global__ __launch_bounds__(256, 1) void outproj_mma(float* __restrict__ Out)
{
    gemm_core<1>(g_attn, g_Weff, g_beff, 1.0f, Out, blockIdx.y * BM, blockIdx.x * BN, 0);
}

// ===================== flash attention, fp16 (no P smem, no shuffles) =====================
// BQ=128 (8 warps x m16), BKV=64, DH=64. Q + double-buffered K/V in smem (half2 words).
constexpr int AQW = 36;                           // stride (words) for all attn tiles
constexpr int AT_Q = 128 * AQW;                   // Q tile words
constexpr int AT_KV = 64 * AQW;                   // one K or V tile (64 rows x 32 words)
constexpr int AT_DYN = (AT_Q + 4 * AT_KV) * 4;    // 55296 B

__global__ __launch_bounds__(256, 2) void attn_mma()
{
    extern __shared__ uint32_t sma[];
    uint32_t* Qs = sma;
    const uint32_t smb = smem_u32(sma);

    const int tid = threadIdx.x, wid = tid >> 5, lane = tid & 31;
    const int lq = lane >> 2, lr = lane & 3;
    const int qt = gridDim.x - 1 - blockIdx.x;    // big tiles first
    const int bh = blockIdx.y;
    const int qbase = qt * 128;
    const int wr0 = wid * 16;                     // warp's local q-row base

    const __half* Kg0 = g_k + (size_t)bh * Sq * Dh;           // [s][dh]
    const __half* Vg0 = g_v + (size_t)bh * Dh * Sq;           // [dh][s]

    // K/V loader mapping: 4 threads per row, 32B (2x16B) each; 64 rows
    const int r4 = tid >> 2, c4h = (tid & 3) << 4;            // half offset 0/16/32/48
    const uint32_t kvso = (uint32_t)(r4 * AQW + (c4h >> 1)) * 4;

    auto issueKV = [&](int kt, int buf) {
        const uint32_t kb = smb + (uint32_t)(AT_Q + 2 * buf * AT_KV) * 4 + kvso;
        const uint32_t vb = kb + (uint32_t)AT_KV * 4;
        const __half* kp = Kg0 + (size_t)(kt * 64 + r4) * Dh + c4h;
        const __half* vp = Vg0 + (size_t)r4 * Sq + kt * 64 + c4h;
#pragma unroll
        for (int i = 0; i < 2; i++) {
            cpa16(kb + i * 16, kp + i * 8);
            cpa16(vb + i * 16, vp + i * 8);
        }
        cpa_commit();
    };

    // Q tile [128 x 64 halves]: 2 thr/row, 64B each
    {
        const __half* Qg = g_q + ((size_t)bh * Sq + qbase) * Dh;
        const int r = tid >> 1, c0h = (tid & 1) << 5;
        const uint32_t qa = smb + (uint32_t)(r * AQW + (c0h >> 1)) * 4;
        const __half* qp = Qg + (size_t)r * Dh + c0h;
#pragma unroll
        for (int i = 0; i < 4; i++) cpa16(qa + i * 16, qp + i * 8);
    }
    issueKV(0, 0);   // commits Q+KV0 as one group

    float m0 = -1e30f, m1 = -1e30f, l0 = 0.f, l1 = 0.f;
    float o[8][4];
#pragma unroll
    for (int nt = 0; nt < 8; nt++)
#pragma unroll
        for (int d = 0; d < 4; d++) o[nt][d] = 0.f;

    const int ktmax = 2 * qt + 1;
    for (int kt = 0; kt <= ktmax; kt++) {
        if (kt < ktmax) { issueKV(kt + 1, (kt + 1) & 1); cpa_wait<1>(); }
        else            { cpa_wait<0>(); }
        __syncthreads();

        const int kvbase = kt * 64;
        if (kvbase <= qbase + wr0 + 15) {           // warp not fully masked
            const uint32_t* Ks = sma + AT_Q + 2 * (kt & 1) * AT_KV;
            const uint32_t* Vs = Ks + AT_KV;

            // S = Q K^T  (4 k16 steps over DH=64)
            float sc[8][4];
#pragma unroll
            for (int nt = 0; nt < 8; nt++)
#pragma unroll
                for (int d = 0; d < 4; d++) sc[nt][d] = 0.f;

            const uint32_t* qb = Qs + (wr0 + lq) * AQW + lr;
            const uint32_t* kb = Ks + lq * AQW + lr;
#pragma unroll
            for (int kk = 0; kk < 32; kk += 8) {
                uint32_t af[4];
                af[0] = qb[kk];
                af[1] = qb[8 * AQW + kk];
                af[2] = qb[kk + 4];
                af[3] = qb[8 * AQW + kk + 4];
#pragma unroll
                for (int nt = 0; nt < 8; nt++) {
                    uint32_t bf[2];
                    bf[0] = kb[nt * 8 * AQW + kk];
                    bf[1] = kb[nt * 8 * AQW + kk + 4];
                    mma16(sc[nt], af, bf);
                }
            }

            // causal mask
            const int row0 = qbase + wr0 + lq, row1 = row0 + 8;
            if (kvbase + 63 > row0) {
#pragma unroll
                for (int nt = 0; nt < 8; nt++) {
                    const int cg = kvbase + nt * 8 + (lr << 1);
                    if (cg > row0)     sc[nt][0] = -1e30f;
                    if (cg + 1 > row0) sc[nt][1] = -1e30f;
                    if (cg > row1)     sc[nt][2] = -1e30f;
                    if (cg + 1 > row1) sc[nt][3] = -1e30f;
                }
            }

            // online softmax (rows row0, row1)
            float mx0 = -1e30f, mx1 = -1e30f;
#pragma unroll
            for (int nt = 0; nt < 8; nt++) {
                mx0 = fmaxf(mx0, fmaxf(sc[nt][0], sc[nt][1]));
                mx1 = fmaxf(mx1, fmaxf(sc[nt][2], sc[nt][3]));
            }
            mx0 = fmaxf(mx0, __shfl_xor_sync(0xffffffffu, mx0, 1));
            mx0 = fmaxf(mx0, __shfl_xor_sync(0xffffffffu, mx0, 2));
            mx1 = fmaxf(mx1, __shfl_xor_sync(0xffffffffu, mx1, 1));
            mx1 = fmaxf(mx1, __shfl_xor_sync(0xffffffffu, mx1, 2));
            const float mn0 = fmaxf(m0, mx0), mn1 = fmaxf(m1, mx1);
            const float cr0 = __expf(m0 - mn0), cr1 = __expf(m1 - mn1);
            float s0 = 0.f, s1 = 0.f;
#pragma unroll
            for (int nt = 0; nt < 8; nt++) {
                sc[nt][0] = __expf(sc[nt][0] - mn0); s0 += sc[nt][0];
                sc[nt][1] = __expf(sc[nt][1] - mn0); s0 += sc[nt][1];
                sc[nt][2] = __expf(sc[nt][2] - mn1); s1 += sc[nt][2];
                sc[nt][3] = __expf(sc[nt][3] - mn1); s1 += sc[nt][3];
            }
            s0 += __shfl_xor_sync(0xffffffffu, s0, 1);
            s0 += __shfl_xor_sync(0xffffffffu, s0, 2);
            s1 += __shfl_xor_sync(0xffffffffu, s1, 1);
            s1 += __shfl_xor_sync(0xffffffffu, s1, 2);
            l0 = l0 * cr0 + s0; m0 = mn0;
            l1 = l1 * cr1 + s1; m1 = mn1;
#pragma unroll
            for (int nt = 0; nt < 8; nt++) {
                o[nt][0] *= cr0; o[nt][1] *= cr0;
                o[nt][2] *= cr1; o[nt][3] *= cr1;
            }

            // O += P V : fp16 c-frag IS the a-frag layout — just pack pairs. 4 k16 steps.
#pragma unroll
            for (int st = 0; st < 4; st++) {
                uint32_t af[4];
                af[0] = h2pack(sc[2 * st][0],     sc[2 * st][1]);
                af[1] = h2pack(sc[2 * st][2],     sc[2 * st][3]);
                af[2] = h2pack(sc[2 * st + 1][0], sc[2 * st + 1][1]);
                af[3] = h2pack(sc[2 * st + 1][2], sc[2 * st + 1][3]);
#pragma unroll
                for (int nt2 = 0; nt2 < 8; nt2++) {
                    const uint32_t* p = Vs + (nt2 * 8 + lq) * AQW + st * 8 + lr;
                    uint32_t bf[2];
                    bf[0] = p[0];
                    bf[1] = p[4];
                    mma16(o[nt2], af, bf);
                }
            }
        }
        __syncthreads();
    }

    // write O (fp16) to g_attn [B,S,D]
    const int b_ = bh >> 4, h_ = bh & 15;
    const int r0g = qbase + wr0 + lq, r1g = r0g + 8;
    const float i0 = 1.0f / l0, i1 = 1.0f / l1;
#pragma unroll
    for (int nt = 0; nt < 8; nt++) {
        const int col = h_ * Dh + nt * 8 + (lr << 1);
        *(uint32_t*)(g_attn + ((size_t)b_ * Sq + r0g) * Dm + col)
            = h2pack(o[nt][0] * i0, o[nt][1] * i0);
        *(uint32_t*)(g_attn + ((size_t)b_ * Sq + r1g) * Dm + col)
            = h2pack(o[nt][2] * i1, o[nt][3] * i1);
    }
}

// ===================== launch =====================
extern "C" void kernel_launch(void* const* d_in, const int* in_sizes, int n_in,
                              void* d_out, int out_size) {
    const float* x    = (const float*)d_in[0];
    const float* w    = (const float*)d_in[1];
    const float* Wq   = (const float*)d_in[2];
    const float* bq   = (const float*)d_in[3];
    const float* Wk   = (const float*)d_in[4];
    const float* bk   = (const float*)d_in[5];
    const float* Wv   = (const float*)d_in[6];
    const float* bv   = (const float*)d_in[7];
    const float* Wout = (const float*)d_in[8];
    const float* bout = (const float*)d_in[9];
    float* out = (float*)d_out;

    prep_kernel<<<2048, 512>>>(w, x, Wq, Wk, Wv, bq, bk, bv, Wout, bout);

    cudaFuncSetAttribute(proj_mma, cudaFuncAttributeMaxDynamicSharedMemorySize, GEMM_DYN);
    proj_mma<<<dim3(3 * Dm / BN, Mrows / BM), 256, GEMM_DYN>>>();

    cudaFuncSetAttribute(attn_mma, cudaFuncAttributeMaxDynamicSharedMemorySize, AT_DYN);
    attn_mma<<<dim3(Sq / 128, Bb * Hh), 256, AT_DYN>>>();

    cudaFuncSetAttribute(outproj_mma, cudaFuncAttributeMaxDynamicSharedMemorySize, GEMM_DYN);
    outproj_mma<<<dim3(Dm / BN, Mrows / BM), 256, GEMM_DYN>>>(out);
}

// round 13
// speedup vs baseline: 6.6553x; 1.0027x over previous
#include <cuda_runtime.h>
#include <cuda_fp16.h>
#include <cstdint>

// Problem constants
constexpr int Bb = 2, Sq = 2048, Dm = 1024, Hh = 16, Dh = 64;
constexpr int Mrows = Bb * Sq; // 4096

// Scratch (no cudaMalloc allowed)
__device__ __half g_q[Bb * Hh * Sq * Dh];     // [B,H,S,DH] fp16, Q pre-scaled by 1/8
__device__ __half g_k[Bb * Hh * Sq * Dh];     // [B,H,S,DH] fp16
__device__ __half g_v[Bb * Hh * Dh * Sq];     // [B,H,DH,S] fp16 (TRANSPOSED)
__device__ __half g_attn[Bb * Sq * Dm];       // fp16
__device__ __half g_Weff[Dm * Dm];            // fp16
__device__ float  g_beff[Dm];                 // fp32
__device__ __half g_xt[Bb * Sq * Dm];         // fp16 x
__device__ __half g_wcat[3 * Dm * Dm];        // fp16 Wq|Wk|Wv
__device__ float  g_bcat[3 * Dm];             // bq|bk|bv fp32

// ===================== helpers =====================
__device__ __forceinline__ uint32_t h2pack(float lo, float hi) {
    __half2 h = __floats2half2_rn(lo, hi);
    return *(uint32_t*)&h;
}
__device__ __forceinline__ uint32_t smem_u32(const void* p) {
    uint32_t a;
    asm("{ .reg .u64 t; cvta.to.shared.u64 t, %1; cvt.u32.u64 %0, t; }" : "=r"(a) : "l"(p));
    return a;
}
__device__ __forceinline__ void cpa16(uint32_t d, const void* s) {
    asm volatile("cp.async.cg.shared.global [%0], [%1], 16;" :: "r"(d), "l"(s));
}
__device__ __forceinline__ void cpa_commit() {
    asm volatile("cp.async.commit_group;" ::: "memory");
}
template <int N>
__device__ __forceinline__ void cpa_wait() {
    asm volatile("cp.async.wait_group %0;" :: "n"(N) : "memory");
}
// D(16x8,f32) += A(16x16 f16) * B(16x8 f16)
__device__ __forceinline__ void mma16(float* c, const uint32_t* a, const uint32_t* b) {
    asm volatile(
        "mma.sync.aligned.m16n8k16.row.col.f32.f16.f16.f32 "
        "{%0,%1,%2,%3}, {%4,%5,%6,%7}, {%8,%9}, {%0,%1,%2,%3};"
        : "+f"(c[0]), "+f"(c[1]), "+f"(c[2]), "+f"(c[3])
        : "r"(a[0]), "r"(a[1]), "r"(a[2]), "r"(a[3]), "r"(b[0]), "r"(b[1]));
}
// 4x m8n8 b16 matrices, warp-collective
__device__ __forceinline__ void ldsm4(uint32_t* r, uint32_t addr) {
    asm volatile("ldmatrix.sync.aligned.m8n8.x4.shared.b16 {%0,%1,%2,%3}, [%4];"
                 : "=r"(r[0]), "=r"(r[1]), "=r"(r[2]), "=r"(r[3]) : "r"(addr));
}

// ===================== prep: fp16 conversions + combines =====================
__global__ void prep_kernel(const float* __restrict__ w,  const float* __restrict__ x,
                            const float* __restrict__ Wq, const float* __restrict__ Wk,
                            const float* __restrict__ Wv,
                            const float* __restrict__ bq, const float* __restrict__ bk,
                            const float* __restrict__ bv,
                            const float* __restrict__ Wout, const float* __restrict__ bout) {
    const float w0 = w[0], w1 = w[1], w2 = w[2], w3 = w[3];
    const float4* x4  = (const float4*)x;
    const float4* wq4 = (const float4*)Wq;
    const float4* wk4 = (const float4*)Wk;
    const float4* wv4 = (const float4*)Wv;
    const float4* wo4 = (const float4*)Wout;
    uint2* xt = (uint2*)g_xt;
    uint2* wc = (uint2*)g_wcat;
    uint2* we = (uint2*)g_Weff;
    constexpr int NX = Mrows * Dm / 4;       // 1048576
    constexpr int NW = Dm * Dm / 4;          // 262144
    for (int i = blockIdx.x * blockDim.x + threadIdx.x; i < NX; i += gridDim.x * blockDim.x) {
        float4 v = x4[i];
        xt[i] = make_uint2(h2pack(v.x, v.y), h2pack(v.z, v.w));
        if (i < NW) {
            float4 a = wq4[i];
            wc[i] = make_uint2(h2pack(a.x, a.y), h2pack(a.z, a.w));
            a = wk4[i];
            wc[i + NW] = make_uint2(h2pack(a.x, a.y), h2pack(a.z, a.w));
            a = wv4[i];
            wc[i + 2 * NW] = make_uint2(h2pack(a.x, a.y), h2pack(a.z, a.w));
            float4 p = wo4[i], q = wo4[i + NW], r = wo4[i + 2 * NW], s = wo4[i + 3 * NW];
            float4 e;
            e.x = w0 * p.x + w1 * q.x + w2 * r.x + w3 * s.x;
            e.y = w0 * p.y + w1 * q.y + w2 * r.y + w3 * s.y;
            e.z = w0 * p.z + w1 * q.z + w2 * r.z + w3 * s.z;
            e.w = w0 * p.w + w1 * q.w + w2 * r.w + w3 * s.w;
            we[i] = make_uint2(h2pack(e.x, e.y), h2pack(e.z, e.w));
        }
        if (i < 3 * Dm) {
            const int z = i >> 10, j = i & 1023;
            g_bcat[i] = (z == 0) ? bq[j] : (z == 1) ? bk[j] : bv[j];
        }
        if (i < Dm) {
            g_beff[i] = w0 * bout[i] + w1 * bout[i + Dm]
                      + w2 * bout[i + 2 * Dm] + w3 * bout[i + 3 * Dm];
        }
    }
}

// ======== fp16 NT GEMM: CTA 256x128, 256 thr, warp tile 64x64, 4-stage ring ========
// Tiles stored as 32-bit words (half2). BK = 64 halves = 32 words per row per stage.
constexpr int BM = 256, BN = 128, BKH = 64, BKW = 32;
constexpr int SKW = BKW + 4;                    // padded stride (words); 144B (ldsm conflict-free)
constexpr int TILEA = BM * SKW;                 // 9216 words
constexpr int TILEB = BN * SKW;                 // 4608 words
constexpr int STAGEU = TILEA + TILEB;           // 13824 words
constexpr int NST = 4;
constexpr int GEMM_DYN = NST * STAGEU * 4;      // 221184 B
constexpr int NSTAGE = Dm / BKH;                // 16

template <int MODE>  // 0 = QKV epilogue (fp16 out, V transposed), 1 = plain fp32
__device__ __forceinline__ void gemm_core(
    const __half* __restrict__ A, const __half* __restrict__ W,
    const float* __restrict__ bias, float scale, void* __restrict__ outp,
    int rowBase, int colBase, int zsel)
{
    extern __shared__ uint32_t smg[];
    const uint32_t smb = smem_u32(smg);
    const int tid = threadIdx.x, wid = tid >> 5, lane = tid & 31;
    const int lq = lane >> 2, lr = lane & 3;
    const int warpM = wid & 3, warpN = wid >> 2;       // 4 x 2 warps, warp tile 64x64

    // Loaders: 2 thr/row, 64B (4x16B) each = 128B/row. A rows 0..127 & 128..255; B 128 rows.
    const int rowL = tid >> 1;
    const int khh = (tid & 1) << 5;                    // half offset 0/32
    const __half* Ap0 = A + (size_t)(rowBase + rowL) * Dm + khh;
    const __half* Ap1 = Ap0 + (size_t)128 * Dm;
    const __half* Bp  = W + (size_t)(colBase + rowL) * Dm + khh;
    const uint32_t saA0 = smb + (uint32_t)(rowL * SKW + (khh >> 1)) * 4;
    const uint32_t saA1 = saA0 + (uint32_t)(128 * SKW) * 4;
    const uint32_t saB  = smb + (uint32_t)(TILEA + rowL * SKW + (khh >> 1)) * 4;

    auto issue = [&](int s) {
        const uint32_t off = (uint32_t)((s % NST) * STAGEU) * 4;
        const __half* ga0 = Ap0 + s * BKH;
        const __half* ga1 = Ap1 + s * BKH;
        const __half* gb  = Bp + s * BKH;
#pragma unroll
        for (int i = 0; i < 4; i++) {
            cpa16(saA0 + off + i * 16, ga0 + i * 8);
            cpa16(saA1 + off + i * 16, ga1 + i * 8);
            cpa16(saB  + off + i * 16, gb  + i * 8);
        }
        cpa_commit();
    };

    // ldmatrix per-lane source offsets (word units)
    const uint32_t aOffW = (uint32_t)((warpM * 64 + (lane & 15)) * SKW + (lane >> 4) * 4);
    const uint32_t bOffW = (uint32_t)(TILEA
                        + (warpN * 64 + (lane & 7) + (lane >> 4) * 8) * SKW
                        + ((lane >> 3) & 1) * 4);

    float c[4][8][4];
#pragma unroll
    for (int a = 0; a < 4; a++)
#pragma unroll
        for (int b = 0; b < 8; b++)
#pragma unroll
            for (int d = 0; d < 4; d++) c[a][b][d] = 0.f;

    issue(0); issue(1); issue(2);

    for (int s = 0; s < NSTAGE; s++) {
        if (s + 2 < NSTAGE) cpa_wait<2>(); else cpa_wait<0>();
        __syncthreads();
        if (s + 3 < NSTAGE) issue(s + 3);

        const uint32_t stW = (uint32_t)((s % NST) * STAGEU);
        const uint32_t aAddr = smb + (stW + aOffW) * 4;
        const uint32_t bAddr = smb + (stW + bOffW) * 4;
#pragma unroll
        for (int kk = 0; kk < BKW; kk += 8) {          // 4 k16 steps
            uint32_t af[4][4], bf[4][4];               // bf[p] covers nt=2p,2p+1
#pragma unroll
            for (int mt = 0; mt < 4; mt++) ldsm4(af[mt], aAddr + (uint32_t)(mt * 16 * SKW + kk) * 4);
#pragma unroll
            for (int p = 0; p < 4; p++) ldsm4(bf[p], bAddr + (uint32_t)(p * 16 * SKW + kk) * 4);
#pragma unroll
            for (int mt = 0; mt < 4; mt++)
#pragma unroll
                for (int nt = 0; nt < 8; nt++)
                    mma16(c[mt][nt], af[mt], bf[nt >> 1] + (nt & 1) * 2);
        }
    }

    // Epilogue. C frag (mt,nt): rows lq (+8), cols lr*2 (+1)
#pragma unroll
    for (int mt = 0; mt < 4; mt++) {
        const int r0 = rowBase + warpM * 64 + mt * 16 + lq;
#pragma unroll
        for (int nt = 0; nt < 8; nt++) {
            const int n = colBase + warpN * 64 + nt * 8 + (lr << 1);
            float bx = bias[n], by = bias[n + 1];
#pragma unroll
            for (int half_ = 0; half_ < 2; half_++) {
                const int m = r0 + half_ * 8;
                float vx = (c[mt][nt][half_ * 2 + 0] + bx) * scale;
                float vy = (c[mt][nt][half_ * 2 + 1] + by) * scale;
                if (MODE == 0) {
                    const int b_ = m >> 11, s_ = m & 2047, h_ = n >> 6, d0 = n & 63;
                    __half* out = (__half*)outp;
                    if (zsel == 2) {   // V: transposed [B,H,DH,S]
                        const size_t base = ((size_t)(b_ * Hh + h_) * Dh + d0) * Sq + s_;
                        out[base] = __float2half_rn(vx);
                        out[base + Sq] = __float2half_rn(vy);
                    } else {           // Q/K: [B,H,S,DH]
                        *(uint32_t*)(out + ((size_t)(b_ * Hh + h_) * Sq + s_) * Dh + d0)
                            = h2pack(vx, vy);
                    }
                } else {
                    *(float2*)((float*)outp + (size_t)m * Dm + n) = make_float2(vx, vy);
                }
            }
        }
    }
}

// Fused QKV projection: N = 3072 (Wq|Wk|Wv)
__global__ __launch_bounds__(256, 1) void proj_mma()
{
    const int nGlob = blockIdx.x * BN;          // 0..2944
    const int z = nGlob >> 10;                  // 0,1,2
    const int colLocal = nGlob & 1023;
    const __half* W   = g_wcat + (size_t)z * Dm * Dm;
    const float* bias = g_bcat + z * Dm;
    __half* out       = (z == 0) ? g_q : (z == 1) ? g_k : g_v;
    const float scale = (z == 0) ? 0.125f : 1.0f;
    gemm_core<0>(g_xt, W, bias, scale, out, blockIdx.y * BM, colLocal, z);
}

__global__ __launch_bounds__(256, 1) void outproj_mma(float* __restrict__ Out)
{
    gemm_core<1>(g_attn, g_Weff, g_beff, 1.0f, Out, blockIdx.y * BM, blockIdx.x * BN, 0);
}

// ===================== flash attention, fp16 + ldmatrix =====================
// BQ=128 (8 warps x m16), BKV=64, DH=64. Q + double-buffered K/V in smem (half2 words).
constexpr int AQW = 36;                           // stride (words); 144B (ldsm conflict-free)
constexpr int AT_Q = 128 * AQW;                   // Q tile words
constexpr int AT_KV = 64 * AQW;                   // one K or V tile (64 rows x 32 words)
constexpr int AT_DYN = (AT_Q + 4 * AT_KV) * 4;    // 55296 B

__global__ __launch_bounds__(256, 2) void attn_mma()
{
    extern __shared__ uint32_t sma[];
    const uint32_t smb = smem_u32(sma);

    const int tid = threadIdx.x, wid = tid >> 5, lane = tid & 31;
    const int lq = lane >> 2, lr = lane & 3;
    const int qt = gridDim.x - 1 - blockIdx.x;    // big tiles first
    const int bh = blockIdx.y;
    const int qbase = qt * 128;
    const int wr0 = wid * 16;                     // warp's local q-row base

    const __half* Kg0 = g_k + (size_t)bh * Sq * Dh;           // [s][dh]
    const __half* Vg0 = g_v + (size_t)bh * Dh * Sq;           // [dh][s]

    // K/V loader mapping: 4 threads per row, 32B (2x16B) each; 64 rows
    const int r4 = tid >> 2, c4h = (tid & 3) << 4;            // half offset 0/16/32/48
    const uint32_t kvso = (uint32_t)(r4 * AQW + (c4h >> 1)) * 4;

    auto issueKV = [&](int kt, int buf) {
        const uint32_t kb = smb + (uint32_t)(AT_Q + 2 * buf * AT_KV) * 4 + kvso;
        const uint32_t vb = kb + (uint32_t)AT_KV * 4;
        const __half* kp = Kg0 + (size_t)(kt * 64 + r4) * Dh + c4h;
        const __half* vp = Vg0 + (size_t)r4 * Sq + kt * 64 + c4h;
#pragma unroll
        for (int i = 0; i < 2; i++) {
            cpa16(kb + i * 16, kp + i * 8);
            cpa16(vb + i * 16, vp + i * 8);
        }
        cpa_commit();
    };

    // Q tile [128 x 64 halves]: 2 thr/row, 64B each
    {
        const __half* Qg = g_q + ((size_t)bh * Sq + qbase) * Dh;
        const int r = tid >> 1, c0h = (tid & 1) << 5;
        const uint32_t qa = smb + (uint32_t)(r * AQW + (c0h >> 1)) * 4;
        const __half* qp = Qg + (size_t)r * Dh + c0h;
#pragma unroll
        for (int i = 0; i < 4; i++) cpa16(qa + i * 16, qp + i * 8);
    }
    issueKV(0, 0);   // commits Q+KV0 as one group

    // ldmatrix per-lane offsets (words)
    const uint32_t qOffW = (uint32_t)((wr0 + (lane & 15)) * AQW + (lane >> 4) * 4);
    const uint32_t kvOffW = (uint32_t)(((lane & 7) + (lane >> 4) * 8) * AQW + ((lane >> 3) & 1) * 4);

    float m0 = -1e30f, m1 = -1e30f, l0 = 0.f, l1 = 0.f;
    float o[8][4];
#pragma unroll
    for (int nt = 0; nt < 8; nt++)
#pragma unroll
        for (int d = 0; d < 4; d++) o[nt][d] = 0.f;

    const int ktmax = 2 * qt + 1;
    for (int kt = 0; kt <= ktmax; kt++) {
        if (kt < ktmax) { issueKV(kt + 1, (kt + 1) & 1); cpa_wait<1>(); }
        else            { cpa_wait<0>(); }
        __syncthreads();

        const int kvbase = kt * 64;
        if (kvbase <= qbase + wr0 + 15) {           // warp not fully masked
            const uint32_t kAddr = smb + (uint32_t)(AT_Q + 2 * (kt & 1) * AT_KV + kvOffW) * 4;
            const uint32_t vAddr = kAddr + (uint32_t)AT_KV * 4;
            const uint32_t qAddr = smb + qOffW * 4;

            // S = Q K^T  (4 k16 steps over DH=64)
            float sc[8][4];
#pragma unroll
            for (int nt = 0; nt < 8; nt++)
#pragma unroll
                for (int d = 0; d < 4; d++) sc[nt][d] = 0.f;

#pragma unroll
            for (int kk = 0; kk < 32; kk += 8) {
                uint32_t af[4], bf[4][4];
                ldsm4(af, qAddr + (uint32_t)kk * 4);
#pragma unroll
                for (int p = 0; p < 4; p++) ldsm4(bf[p], kAddr + (uint32_t)(p * 16 * AQW + kk) * 4);
#pragma unroll
                for (int nt = 0; nt < 8; nt++)
                    mma16(sc[nt], af, bf[nt >> 1] + (nt & 1) * 2);
            }

            // causal mask
            const int row0 = qbase + wr0 + lq, row1 = row0 + 8;
            if (kvbase + 63 > row0) {
#pragma unroll
                for (int nt = 0; nt < 8; nt++) {
                    const int cg = kvbase + nt * 8 + (lr << 1);
                    if (cg > row0)     sc[nt][0] = -1e30f;
                    if (cg + 1 > row0) sc[nt][1] = -1e30f;
                    if (cg > row1)     sc[nt][2] = -1e30f;
                    if (cg + 1 > row1) sc[nt][3] = -1e30f;
                }
            }

            // online softmax (rows row0, row1)
            float mx0 = -1e30f, mx1 = -1e30f;
#pragma unroll
            for (int nt = 0; nt < 8; nt++) {
                mx0 = fmaxf(mx0, fmaxf(sc[nt][0], sc[nt][1]));
                mx1 = fmaxf(mx1, fmaxf(sc[nt][2], sc[nt][3]));
            }
            mx0 = fmaxf(mx0, __shfl_xor_sync(0xffffffffu, mx0, 1));
            mx0 = fmaxf(mx0, __shfl_xor_sync(0xffffffffu, mx0, 2));
            mx1 = fmaxf(mx1, __shfl_xor_sync(0xffffffffu, mx1, 1));
            mx1 = fmaxf(mx1, __shfl_xor_sync(0xffffffffu, mx1, 2));
            const float mn0 = fmaxf(m0, mx0), mn1 = fmaxf(m1, mx1);
            const float cr0 = __expf(m0 - mn0), cr1 = __expf(m1 - mn1);
            float s0 = 0.f, s1 = 0.f;
#pragma unroll
            for (int nt = 0; nt < 8; nt++) {
                sc[nt][0] = __expf(sc[nt][0] - mn0); s0 += sc[nt][0];
                sc[nt][1] = __expf(sc[nt][1] - mn0); s0 += sc[nt][1];
                sc[nt][2] = __expf(sc[nt][2] - mn1); s1 += sc[nt][2];
                sc[nt][3] = __expf(sc[nt][3] - mn1); s1 += sc[nt][3];
            }
            s0 += __shfl_xor_sync(0xffffffffu, s0, 1);
            s0 += __shfl_xor_sync(0xffffffffu, s0, 2);
            s1 += __shfl_xor_sync(0xffffffffu, s1, 1);
            s1 += __shfl_xor_sync(0xffffffffu, s1, 2);
            l0 = l0 * cr0 + s0; m0 = mn0;
            l1 = l1 * cr1 + s1; m1 = mn1;
#pragma unroll
            for (int nt = 0; nt < 8; nt++) {
                o[nt][0] *= cr0; o[nt][1] *= cr0;
                o[nt][2] *= cr1; o[nt][3] *= cr1;
            }

            // O += P V : fp16 c-frag IS the a-frag layout. 4 k16 steps, ldmatrix B.
#pragma unroll
            for (int st = 0; st < 4; st++) {
                uint32_t af[4], bf[4][4];
                af[0] = h2pack(sc[2 * st][0],     sc[2 * st][1]);
                af[1] = h2pack(sc[2 * st][2],     sc[2 * st][3]);
                af[2] = h2pack(sc[2 * st + 1][0], sc[2 * st + 1][1]);
                af[3] = h2pack(sc[2 * st + 1][2], sc[2 * st + 1][3]);
#pragma unroll
                for (int p = 0; p < 4; p++) ldsm4(bf[p], vAddr + (uint32_t)(p * 16 * AQW + st * 8) * 4);
#pragma unroll
                for (int nt2 = 0; nt2 < 8; nt2++)
                    mma16(o[nt2], af, bf[nt2 >> 1] + (nt2 & 1) * 2);
            }
        }
        __syncthreads();
    }

    // write O (fp16) to g_attn [B,S,D]
    const int b_ = bh >> 4, h_ = bh & 15;
    const int r0g = qbase + wr0 + lq, r1g = r0g + 8;
    const float i0 = 1.0f / l0, i1 = 1.0f / l1;
#pragma unroll
    for (int nt = 0; nt < 8; nt++) {
        const int col = h_ * Dh + nt * 8 + (lr << 1);
        *(uint32_t*)(g_attn + ((size_t)b_ * Sq + r0g) * Dm + col)
            = h2pack(o[nt][0] * i0, o[nt][1] * i0);
        *(uint32_t*)(g_attn + ((size_t)b_ * Sq + r1g) * Dm + col)
            = h2pack(o[nt][2] * i1, o[nt][3] * i1);
    }
}

// ===================== launch =====================
extern "C" void kernel_launch(void* const* d_in, const int* in_sizes, int n_in,
                              void* d_out, int out_size) {
    const float* x    = (const float*)d_in[0];
    const float* w    = (const float*)d_in[1];
    const float* Wq   = (const float*)d_in[2];
    const float* bq   = (const float*)d_in[3];
    const float* Wk   = (const float*)d_in[4];
    const float* bk   = (const float*)d_in[5];
    const float* Wv   = (const float*)d_in[6];
    const float* bv   = (const float*)d_in[7];
    const float* Wout = (const float*)d_in[8];
    const float* bout = (const float*)d_in[9];
    float* out = (float*)d_out;

    prep_kernel<<<2048, 512>>>(w, x, Wq, Wk, Wv, bq, bk, bv, Wout, bout);

    cudaFuncSetAttribute(proj_mma, cudaFuncAttributeMaxDynamicSharedMemorySize, GEMM_DYN);
    proj_mma<<<dim3(3 * Dm / BN, Mrows / BM), 256, GEMM_DYN>>>();

    cudaFuncSetAttribute(attn_mma, cudaFuncAttributeMaxDynamicSharedMemorySize, AT_DYN);
    attn_mma<<<dim3(Sq / 128, Bb * Hh), 256, AT_DYN>>>();

    cudaFuncSetAttribute(outproj_mma, cudaFuncAttributeMaxDynamicSharedMemorySize, GEMM_DYN);
    outproj_mma<<<dim3(Dm / BN, Mrows / BM), 256, GEMM_DYN>>>(out);
}

// round 14
// speedup vs baseline: 6.6602x; 1.0007x over previous
#include <cuda_runtime.h>
#include <cuda_fp16.h>
#include <cstdint>

// Problem constants
constexpr int Bb = 2, Sq = 2048, Dm = 1024, Hh = 16, Dh = 64;
constexpr int Mrows = Bb * Sq; // 4096

// Scratch (no cudaMalloc allowed)
__device__ __half g_q[Bb * Hh * Sq * Dh];     // [B,H,S,DH] fp16, Q pre-scaled by 1/8
__device__ __half g_k[Bb * Hh * Sq * Dh];     // [B,H,S,DH] fp16
__device__ __half g_v[Bb * Hh * Dh * Sq];     // [B,H,DH,S] fp16 (TRANSPOSED)
__device__ __half g_attn[Bb * Sq * Dm];       // fp16
__device__ __half g_Weff[Dm * Dm];            // fp16
__device__ float  g_beff[Dm];                 // fp32
__device__ __half g_xt[Bb * Sq * Dm];         // fp16 x
__device__ __half g_wcat[3 * Dm * Dm];        // fp16 Wq|Wk|Wv
__device__ float  g_bcat[3 * Dm];             // bq|bk|bv fp32

// ===================== helpers =====================
__device__ __forceinline__ uint32_t h2pack(float lo, float hi) {
    __half2 h = __floats2half2_rn(lo, hi);
    return *(uint32_t*)&h;
}
__device__ __forceinline__ uint32_t smem_u32(const void* p) {
    uint32_t a;
    asm("{ .reg .u64 t; cvta.to.shared.u64 t, %1; cvt.u32.u64 %0, t; }" : "=r"(a) : "l"(p));
    return a;
}
__device__ __forceinline__ void cpa16(uint32_t d, const void* s) {
    asm volatile("cp.async.cg.shared.global [%0], [%1], 16;" :: "r"(d), "l"(s));
}
__device__ __forceinline__ void cpa_commit() {
    asm volatile("cp.async.commit_group;" ::: "memory");
}
template <int N>
__device__ __forceinline__ void cpa_wait() {
    asm volatile("cp.async.wait_group %0;" :: "n"(N) : "memory");
}
// D(16x8,f32) += A(16x16 f16) * B(16x8 f16)
__device__ __forceinline__ void mma16(float* c, const uint32_t* a, const uint32_t* b) {
    asm volatile(
        "mma.sync.aligned.m16n8k16.row.col.f32.f16.f16.f32 "
        "{%0,%1,%2,%3}, {%4,%5,%6,%7}, {%8,%9}, {%0,%1,%2,%3};"
        : "+f"(c[0]), "+f"(c[1]), "+f"(c[2]), "+f"(c[3])
        : "r"(a[0]), "r"(a[1]), "r"(a[2]), "r"(a[3]), "r"(b[0]), "r"(b[1]));
}
// 4x m8n8 b16 matrices, warp-collective
__device__ __forceinline__ void ldsm4(uint32_t* r, uint32_t addr) {
    asm volatile("ldmatrix.sync.aligned.m8n8.x4.shared.b16 {%0,%1,%2,%3}, [%4];"
                 : "=r"(r[0]), "=r"(r[1]), "=r"(r[2]), "=r"(r[3]) : "r"(addr));
}

// ===================== prep: fp16 conversions + combines =====================
__global__ void prep_kernel(const float* __restrict__ w,  const float* __restrict__ x,
                            const float* __restrict__ Wq, const float* __restrict__ Wk,
                            const float* __restrict__ Wv,
                            const float* __restrict__ bq, const float* __restrict__ bk,
                            const float* __restrict__ bv,
                            const float* __restrict__ Wout, const float* __restrict__ bout) {
    const float w0 = w[0], w1 = w[1], w2 = w[2], w3 = w[3];
    const float4* x4  = (const float4*)x;
    const float4* wq4 = (const float4*)Wq;
    const float4* wk4 = (const float4*)Wk;
    const float4* wv4 = (const float4*)Wv;
    const float4* wo4 = (const float4*)Wout;
    uint2* xt = (uint2*)g_xt;
    uint2* wc = (uint2*)g_wcat;
    uint2* we = (uint2*)g_Weff;
    constexpr int NX = Mrows * Dm / 4;       // 1048576
    constexpr int NW = Dm * Dm / 4;          // 262144
    for (int i = blockIdx.x * blockDim.x + threadIdx.x; i < NX; i += gridDim.x * blockDim.x) {
        float4 v = x4[i];
        xt[i] = make_uint2(h2pack(v.x, v.y), h2pack(v.z, v.w));
        if (i < NW) {
            float4 a = wq4[i];
            wc[i] = make_uint2(h2pack(a.x, a.y), h2pack(a.z, a.w));
            a = wk4[i];
            wc[i + NW] = make_uint2(h2pack(a.x, a.y), h2pack(a.z, a.w));
            a = wv4[i];
            wc[i + 2 * NW] = make_uint2(h2pack(a.x, a.y), h2pack(a.z, a.w));
            float4 p = wo4[i], q = wo4[i + NW], r = wo4[i + 2 * NW], s = wo4[i + 3 * NW];
            float4 e;
            e.x = w0 * p.x + w1 * q.x + w2 * r.x + w3 * s.x;
            e.y = w0 * p.y + w1 * q.y + w2 * r.y + w3 * s.y;
            e.z = w0 * p.z + w1 * q.z + w2 * r.z + w3 * s.z;
            e.w = w0 * p.w + w1 * q.w + w2 * r.w + w3 * s.w;
            we[i] = make_uint2(h2pack(e.x, e.y), h2pack(e.z, e.w));
        }
        if (i < 3 * Dm) {
            const int z = i >> 10, j = i & 1023;
            g_bcat[i] = (z == 0) ? bq[j] : (z == 1) ? bk[j] : bv[j];
        }
        if (i < Dm) {
            g_beff[i] = w0 * bout[i] + w1 * bout[i + Dm]
                      + w2 * bout[i + 2 * Dm] + w3 * bout[i + 3 * Dm];
        }
    }
}

// ======== fp16 NT GEMM: CTA 256x128, 256 thr, warp tile 64x64, 4-stage ring ========
// Tiles stored as 32-bit words (half2). BK = 64 halves = 32 words per row per stage.
constexpr int BM = 256, BN = 128, BKH = 64, BKW = 32;
constexpr int SKW = BKW + 4;                    // padded stride (words); 144B (ldsm conflict-free)
constexpr int TILEA = BM * SKW;                 // 9216 words
constexpr int TILEB = BN * SKW;                 // 4608 words
constexpr int STAGEU = TILEA + TILEB;           // 13824 words
constexpr int NST = 4;
constexpr int GEMM_DYN = NST * STAGEU * 4;      // 221184 B
constexpr int NSTAGE = Dm / BKH;                // 16

template <int MODE>  // 0 = QKV epilogue (fp16 out, V transposed), 1 = plain fp32
__device__ __forceinline__ void gemm_core(
    const __half* __restrict__ A, const __half* __restrict__ W,
    const float* __restrict__ bias, float scale, void* __restrict__ outp,
    int rowBase, int colBase, int zsel)
{
    extern __shared__ uint32_t smg[];
    const uint32_t smb = smem_u32(smg);
    const int tid = threadIdx.x, wid = tid >> 5, lane = tid & 31;
    const int lq = lane >> 2, lr = lane & 3;
    const int warpM = wid & 3, warpN = wid >> 2;       // 4 x 2 warps, warp tile 64x64

    // Loaders: 2 thr/row, 64B (4x16B) each = 128B/row. A rows 0..127 & 128..255; B 128 rows.
    const int rowL = tid >> 1;
    const int khh = (tid & 1) << 5;                    // half offset 0/32
    const __half* Ap0 = A + (size_t)(rowBase + rowL) * Dm + khh;
    const __half* Ap1 = Ap0 + (size_t)128 * Dm;
    const __half* Bp  = W + (size_t)(colBase + rowL) * Dm + khh;
    const uint32_t saA0 = smb + (uint32_t)(rowL * SKW + (khh >> 1)) * 4;
    const uint32_t saA1 = saA0 + (uint32_t)(128 * SKW) * 4;
    const uint32_t saB  = smb + (uint32_t)(TILEA + rowL * SKW + (khh >> 1)) * 4;

    auto issue = [&](int s) {
        const uint32_t off = (uint32_t)((s % NST) * STAGEU) * 4;
        const __half* ga0 = Ap0 + s * BKH;
        const __half* ga1 = Ap1 + s * BKH;
        const __half* gb  = Bp + s * BKH;
#pragma unroll
        for (int i = 0; i < 4; i++) {
            cpa16(saA0 + off + i * 16, ga0 + i * 8);
            cpa16(saA1 + off + i * 16, ga1 + i * 8);
            cpa16(saB  + off + i * 16, gb  + i * 8);
        }
        cpa_commit();
    };

    // ldmatrix per-lane source offsets (word units)
    const uint32_t aOffW = (uint32_t)((warpM * 64 + (lane & 15)) * SKW + (lane >> 4) * 4);
    const uint32_t bOffW = (uint32_t)(TILEA
                        + (warpN * 64 + (lane & 7) + (lane >> 4) * 8) * SKW
                        + ((lane >> 3) & 1) * 4);

    float c[4][8][4];
#pragma unroll
    for (int a = 0; a < 4; a++)
#pragma unroll
        for (int b = 0; b < 8; b++)
#pragma unroll
            for (int d = 0; d < 4; d++) c[a][b][d] = 0.f;

    issue(0); issue(1); issue(2);

    for (int s = 0; s < NSTAGE; s++) {
        if (s + 2 < NSTAGE) cpa_wait<2>(); else cpa_wait<0>();
        __syncthreads();
        if (s + 3 < NSTAGE) issue(s + 3);

        const uint32_t stW = (uint32_t)((s % NST) * STAGEU);
        const uint32_t aAddr = smb + (stW + aOffW) * 4;
        const uint32_t bAddr = smb + (stW + bOffW) * 4;
#pragma unroll
        for (int kk = 0; kk < BKW; kk += 8) {          // 4 k16 steps
            uint32_t af[4][4], bf[4][4];               // bf[p] covers nt=2p,2p+1
#pragma unroll
            for (int mt = 0; mt < 4; mt++) ldsm4(af[mt], aAddr + (uint32_t)(mt * 16 * SKW + kk) * 4);
#pragma unroll
            for (int p = 0; p < 4; p++) ldsm4(bf[p], bAddr + (uint32_t)(p * 16 * SKW + kk) * 4);
#pragma unroll
            for (int mt = 0; mt < 4; mt++)
#pragma unroll
                for (int nt = 0; nt < 8; nt++)
                    mma16(c[mt][nt], af[mt], bf[nt >> 1] + (nt & 1) * 2);
        }
    }

    // Epilogue. C frag (mt,nt): rows lq (+8), cols lr*2 (+1)
#pragma unroll
    for (int mt = 0; mt < 4; mt++) {
        const int r0 = rowBase + warpM * 64 + mt * 16 + lq;
#pragma unroll
        for (int nt = 0; nt < 8; nt++) {
            const int n = colBase + warpN * 64 + nt * 8 + (lr << 1);
            float bx = bias[n], by = bias[n + 1];
#pragma unroll
            for (int half_ = 0; half_ < 2; half_++) {
                const int m = r0 + half_ * 8;
                float vx = (c[mt][nt][half_ * 2 + 0] + bx) * scale;
                float vy = (c[mt][nt][half_ * 2 + 1] + by) * scale;
                if (MODE == 0) {
                    const int b_ = m >> 11, s_ = m & 2047, h_ = n >> 6, d0 = n & 63;
                    __half* out = (__half*)outp;
                    if (zsel == 2) {   // V: transposed [B,H,DH,S]
                        const size_t base = ((size_t)(b_ * Hh + h_) * Dh + d0) * Sq + s_;
                        out[base] = __float2half_rn(vx);
                        out[base + Sq] = __float2half_rn(vy);
                    } else {           // Q/K: [B,H,S,DH]
                        *(uint32_t*)(out + ((size_t)(b_ * Hh + h_) * Sq + s_) * Dh + d0)
                            = h2pack(vx, vy);
                    }
                } else {
                    *(float2*)((float*)outp + (size_t)m * Dm + n) = make_float2(vx, vy);
                }
            }
        }
    }
}

// Fused QKV projection: N = 3072 (Wq|Wk|Wv)
__global__ __launch_bounds__(256, 1) void proj_mma()
{
    const int nGlob = blockIdx.x * BN;          // 0..2944
    const int z = nGlob >> 10;                  // 0,1,2
    const int colLocal = nGlob & 1023;
    const __half* W   = g_wcat + (size_t)z * Dm * Dm;
    const float* bias = g_bcat + z * Dm;
    __half* out       = (z == 0) ? g_q : (z == 1) ? g_k : g_v;
    const float scale = (z == 0) ? 0.125f : 1.0f;
    gemm_core<0>(g_xt, W, bias, scale, out, blockIdx.y * BM, colLocal, z);
}

__global__ __launch_bounds__(256, 1) void outproj_mma(float* __restrict__ Out)
{
    gemm_core<1>(g_attn, g_Weff, g_beff, 1.0f, Out, blockIdx.y * BM, blockIdx.x * BN, 0);
}

// ===================== flash attention, fp16 + ldmatrix =====================
// BQ=128 (8 warps x m16), BKV=64, DH=64. Q + double-buffered K/V in smem (half2 words).
constexpr int AQW = 36;                           // stride (words); 144B (ldsm conflict-free)
constexpr int AT_Q = 128 * AQW;                   // Q tile words
constexpr int AT_KV = 64 * AQW;                   // one K or V tile (64 rows x 32 words)
constexpr int AT_DYN = (AT_Q + 4 * AT_KV) * 4;    // 55296 B

__global__ __launch_bounds__(256, 2) void attn_mma()
{
    extern __shared__ uint32_t sma[];
    const uint32_t smb = smem_u32(sma);

    const int tid = threadIdx.x, wid = tid >> 5, lane = tid & 31;
    const int lq = lane >> 2, lr = lane & 3;
    const int qt = gridDim.x - 1 - blockIdx.x;    // big tiles first
    const int bh = blockIdx.y;
    const int qbase = qt * 128;
    const int wr0 = wid * 16;                     // warp's local q-row base

    const __half* Kg0 = g_k + (size_t)bh * Sq * Dh;           // [s][dh]
    const __half* Vg0 = g_v + (size_t)bh * Dh * Sq;           // [dh][s]

    // K/V loader mapping: 4 threads per row, 32B (2x16B) each; 64 rows
    const int r4 = tid >> 2, c4h = (tid & 3) << 4;            // half offset 0/16/32/48
    const uint32_t kvso = (uint32_t)(r4 * AQW + (c4h >> 1)) * 4;

    auto issueKV = [&](int kt, int buf) {
        const uint32_t kb = smb + (uint32_t)(AT_Q + 2 * buf * AT_KV) * 4 + kvso;
        const uint32_t vb = kb + (uint32_t)AT_KV * 4;
        const __half* kp = Kg0 + (size_t)(kt * 64 + r4) * Dh + c4h;
        const __half* vp = Vg0 + (size_t)r4 * Sq + kt * 64 + c4h;
#pragma unroll
        for (int i = 0; i < 2; i++) {
            cpa16(kb + i * 16, kp + i * 8);
            cpa16(vb + i * 16, vp + i * 8);
        }
        cpa_commit();
    };

    // Q tile [128 x 64 halves]: 2 thr/row, 64B each
    {
        const __half* Qg = g_q + ((size_t)bh * Sq + qbase) * Dh;
        const int r = tid >> 1, c0h = (tid & 1) << 5;
        const uint32_t qa = smb + (uint32_t)(r * AQW + (c0h >> 1)) * 4;
        const __half* qp = Qg + (size_t)r * Dh + c0h;
#pragma unroll
        for (int i = 0; i < 4; i++) cpa16(qa + i * 16, qp + i * 8);
    }
    issueKV(0, 0);   // commits Q+KV0 as one group

    // ldmatrix per-lane offsets (words)
    const uint32_t qOffW = (uint32_t)((wr0 + (lane & 15)) * AQW + (lane >> 4) * 4);
    const uint32_t kvOffW = (uint32_t)(((lane & 7) + (lane >> 4) * 8) * AQW + ((lane >> 3) & 1) * 4);

    float m0 = -1e30f, m1 = -1e30f, l0 = 0.f, l1 = 0.f;
    float o[8][4];
#pragma unroll
    for (int nt = 0; nt < 8; nt++)
#pragma unroll
        for (int d = 0; d < 4; d++) o[nt][d] = 0.f;

    const int ktmax = 2 * qt + 1;
    for (int kt = 0; kt <= ktmax; kt++) {
        if (kt < ktmax) { issueKV(kt + 1, (kt + 1) & 1); cpa_wait<1>(); }
        else            { cpa_wait<0>(); }
        __syncthreads();

        const int kvbase = kt * 64;
        if (kvbase <= qbase + wr0 + 15) {           // warp not fully masked
            const uint32_t kAddr = smb + (uint32_t)(AT_Q + 2 * (kt & 1) * AT_KV + kvOffW) * 4;
            const uint32_t vAddr = kAddr + (uint32_t)AT_KV * 4;
            const uint32_t qAddr = smb + qOffW * 4;

            // S = Q K^T  (4 k16 steps over DH=64)
            float sc[8][4];
#pragma unroll
            for (int nt = 0; nt < 8; nt++)
#pragma unroll
                for (int d = 0; d < 4; d++) sc[nt][d] = 0.f;

#pragma unroll
            for (int kk = 0; kk < 32; kk += 8) {
                uint32_t af[4], bf[4][4];
                ldsm4(af, qAddr + (uint32_t)kk * 4);
#pragma unroll
                for (int p = 0; p < 4; p++) ldsm4(bf[p], kAddr + (uint32_t)(p * 16 * AQW + kk) * 4);
#pragma unroll
                for (int nt = 0; nt < 8; nt++)
                    mma16(sc[nt], af, bf[nt >> 1] + (nt & 1) * 2);
            }

            // causal mask
            const int row0 = qbase + wr0 + lq, row1 = row0 + 8;
            if (kvbase + 63 > row0) {
#pragma unroll
                for (int nt = 0; nt < 8; nt++) {
                    const int cg = kvbase + nt * 8 + (lr << 1);
                    if (cg > row0)     sc[nt][0] = -1e30f;
                    if (cg + 1 > row0) sc[nt][1] = -1e30f;
                    if (cg > row1)     sc[nt][2] = -1e30f;
                    if (cg + 1 > row1) sc[nt][3] = -1e30f;
                }
            }

            // online softmax (rows row0, row1)
            float mx0 = -1e30f, mx1 = -1e30f;
#pragma unroll
            for (int nt = 0; nt < 8; nt++) {
                mx0 = fmaxf(mx0, fmaxf(sc[nt][0], sc[nt][1]));
                mx1 = fmaxf(mx1, fmaxf(sc[nt][2], sc[nt][3]));
            }
            mx0 = fmaxf(mx0, __shfl_xor_sync(0xffffffffu, mx0, 1));
            mx0 = fmaxf(mx0, __shfl_xor_sync(0xffffffffu, mx0, 2));
            mx1 = fmaxf(mx1, __shfl_xor_sync(0xffffffffu, mx1, 1));
            mx1 = fmaxf(mx1, __shfl_xor_sync(0xffffffffu, mx1, 2));
            const float mn0 = fmaxf(m0, mx0), mn1 = fmaxf(m1, mx1);
            const float cr0 = __expf(m0 - mn0), cr1 = __expf(m1 - mn1);
            float s0 = 0.f, s1 = 0.f;
#pragma unroll
            for (int nt = 0; nt < 8; nt++) {
                sc[nt][0] = __expf(sc[nt][0] - mn0); s0 += sc[nt][0];
                sc[nt][1] = __expf(sc[nt][1] - mn0); s0 += sc[nt][1];
                sc[nt][2] = __expf(sc[nt][2] - mn1); s1 += sc[nt][2];
                sc[nt][3] = __expf(sc[nt][3] - mn1); s1 += sc[nt][3];
            }
            s0 += __shfl_xor_sync(0xffffffffu, s0, 1);
            s0 += __shfl_xor_sync(0xffffffffu, s0, 2);
            s1 += __shfl_xor_sync(0xffffffffu, s1, 1);
            s1 += __shfl_xor_sync(0xffffffffu, s1, 2);
            l0 = l0 * cr0 + s0; m0 = mn0;
            l1 = l1 * cr1 + s1; m1 = mn1;
#pragma unroll
            for (int nt = 0; nt < 8; nt++) {
                o[nt][0] *= cr0; o[nt][1] *= cr0;
                o[nt][2] *= cr1; o[nt][3] *= cr1;
            }

            // O += P V : fp16 c-frag IS the a-frag layout. 4 k16 steps, ldmatrix B.
#pragma unroll
            for (int st = 0; st < 4; st++) {
                uint32_t af[4], bf[4][4];
                af[0] = h2pack(sc[2 * st][0],     sc[2 * st][1]);
                af[1] = h2pack(sc[2 * st][2],     sc[2 * st][3]);
                af[2] = h2pack(sc[2 * st + 1][0], sc[2 * st + 1][1]);
                af[3] = h2pack(sc[2 * st + 1][2], sc[2 * st + 1][3]);
#pragma unroll
                for (int p = 0; p < 4; p++) ldsm4(bf[p], vAddr + (uint32_t)(p * 16 * AQW + st * 8) * 4);
#pragma unroll
                for (int nt2 = 0; nt2 < 8; nt2++)
                    mma16(o[nt2], af, bf[nt2 >> 1] + (nt2 & 1) * 2);
            }
        }
        __syncthreads();
    }

    // write O (fp16) to g_attn [B,S,D]
    const int b_ = bh >> 4, h_ = bh & 15;
    const int r0g = qbase + wr0 + lq, r1g = r0g + 8;
    const float i0 = 1.0f / l0, i1 = 1.0f / l1;
#pragma unroll
    for (int nt = 0; nt < 8; nt++) {
        const int col = h_ * Dh + nt * 8 + (lr << 1);
        *(uint32_t*)(g_attn + ((size_t)b_ * Sq + r0g) * Dm + col)
            = h2pack(o[nt][0] * i0, o[nt][1] * i0);
        *(uint32_t*)(g_attn + ((size_t)b_ * Sq + r1g) * Dm + col)
            = h2pack(o[nt][2] * i1, o[nt][3] * i1);
    }
}

// ===================== launch =====================
extern "C" void kernel_launch(void* const* d_in, const int* in_sizes, int n_in,
                              void* d_out, int out_size) {
    const float* x    = (const float*)d_in[0];
    const float* w    = (const float*)d_in[1];
    const float* Wq   = (const float*)d_in[2];
    const float* bq   = (const float*)d_in[3];
    const float* Wk   = (const float*)d_in[4];
    const float* bk   = (const float*)d_in[5];
    const float* Wv   = (const float*)d_in[6];
    const float* bv   = (const float*)d_in[7];
    const float* Wout = (const float*)d_in[8];
    const float* bout = (const float*)d_in[9];
    float* out = (float*)d_out;

    prep_kernel<<<2048, 512>>>(w, x, Wq, Wk, Wv, bq, bk, bv, Wout, bout);

    cudaFuncSetAttribute(proj_mma, cudaFuncAttributeMaxDynamicSharedMemorySize, GEMM_DYN);
    proj_mma<<<dim3(3 * Dm / BN, Mrows / BM), 256, GEMM_DYN>>>();

    cudaFuncSetAttribute(attn_mma, cudaFuncAttributeMaxDynamicSharedMemorySize, AT_DYN);
    attn_mma<<<dim3(Sq / 128, Bb * Hh), 256, AT_DYN>>>();

    cudaFuncSetAttribute(outproj_mma, cudaFuncAttributeMaxDynamicSharedMemorySize, GEMM_DYN);
    outproj_mma<<<dim3(Dm / BN, Mrows / BM), 256, GEMM_DYN>>>(out);
}